// round 1
// baseline (speedup 1.0000x reference)
#include <cuda_runtime.h>
#include <cuda_bf16.h>
#include <math.h>

// Problem constants
#define BATCH 4
#define NQ    1024
#define NKV   2048
#define HDIM  1024
#define NH    16
#define DHEAD 64
#define NEXP  4
#define IDIM  1024   // H*4/E

// ---------------------------------------------------------------------------
// Scratch (device globals — no allocations allowed)
// ---------------------------------------------------------------------------
__device__ float g_xln  [BATCH*NQ*HDIM];        // 16 MB
__device__ float g_q    [BATCH*NQ*HDIM];        // 16 MB
__device__ float g_k    [BATCH*NKV*HDIM];       // 32 MB
__device__ float g_v    [BATCH*NKV*HDIM];       // 32 MB
__device__ float g_ctx  [BATCH*NQ*HDIM];        // 16 MB
__device__ float g_res  [BATCH*NQ*HDIM];        // 16 MB
__device__ float g_he   [BATCH*NQ*HDIM];        // 16 MB (expert-grouped LN2 out)
__device__ float g_gu   [BATCH*NQ*2*IDIM];      // 32 MB
__device__ float g_int  [BATCH*NQ*IDIM];        // 16 MB

// ---------------------------------------------------------------------------
// LayerNorm (one block per row of 1024). scatter=1 writes expert-grouped rows.
// ---------------------------------------------------------------------------
__global__ __launch_bounds__(256) void ln_kernel(
    const float* __restrict__ x, const float* __restrict__ g,
    const float* __restrict__ be, float* __restrict__ out, int scatter)
{
    const int row = blockIdx.x;
    const int tid = threadIdx.x;
    const float* xr = x + (long)row * HDIM;

    float4 v = *(const float4*)&xr[tid * 4];
    float s  = v.x + v.y + v.z + v.w;
    float s2 = v.x*v.x + v.y*v.y + v.z*v.z + v.w*v.w;

    #pragma unroll
    for (int off = 16; off; off >>= 1) {
        s  += __shfl_xor_sync(0xffffffffu, s,  off);
        s2 += __shfl_xor_sync(0xffffffffu, s2, off);
    }
    __shared__ float rs[8], rs2[8];
    int w = tid >> 5, lane = tid & 31;
    if (lane == 0) { rs[w] = s; rs2[w] = s2; }
    __syncthreads();
    float tot = 0.f, tot2 = 0.f;
    #pragma unroll
    for (int i = 0; i < 8; i++) { tot += rs[i]; tot2 += rs2[i]; }

    float mu   = tot * (1.0f / HDIM);
    float var  = tot2 * (1.0f / HDIM) - mu * mu;
    float rstd = rsqrtf(var + 1e-6f);

    int orow = row;
    if (scatter) {
        int b = row >> 10, q = row & 1023;
        orow = (q & 3) * (BATCH * NQ / NEXP) + b * (NQ / NEXP) + (q >> 2);
    }
    float4 gv = *(const float4*)&g[tid * 4];
    float4 bv = *(const float4*)&be[tid * 4];
    float4 y;
    y.x = (v.x - mu) * rstd * gv.x + bv.x;
    y.y = (v.y - mu) * rstd * gv.y + bv.y;
    y.z = (v.z - mu) * rstd * gv.z + bv.z;
    y.w = (v.w - mu) * rstd * gv.w + bv.w;
    *(float4*)&out[(long)orow * HDIM + tid * 4] = y;
}

// ---------------------------------------------------------------------------
// SGEMM: C[M,N] = A[M,K] @ B[K,N] (+bias) with epilogue modes.
//   mode 0: C = AB + bias
//   mode 1: C = AB + bias + res[m*N+n]
//   mode 2: (MoE down) grow = b*NQ + 4*j + e; C[grow*H+n] = res[grow*H+n] + AB
// blockIdx.z = expert index; A/B/C advanced by sA/sB/sC per z.
// ---------------------------------------------------------------------------
#define BM 128
#define BN 128
#define BK 16

__global__ __launch_bounds__(256) void sgemm_kernel(
    const float* __restrict__ A, const float* __restrict__ B,
    const float* __restrict__ bias, const float* __restrict__ res,
    float* __restrict__ C, int M, int N, int K, int mode,
    long sA, long sB, long sC)
{
    __shared__ float As[BK][BM + 4];
    __shared__ float Bs[BK][BN + 4];

    const int z = blockIdx.z;
    A += (long)z * sA;
    B += (long)z * sB;
    C += (long)z * sC;

    const int m0  = blockIdx.y * BM;
    const int n0  = blockIdx.x * BN;
    const int tid = threadIdx.x;
    const int tx  = tid & 15;
    const int ty  = tid >> 4;

    const int arow = tid >> 1;
    const int acol = (tid & 1) * 8;
    const int brow = ty;            // 0..15
    const int bcol = tx * 8;

    float acc[8][8];
    #pragma unroll
    for (int i = 0; i < 8; i++)
        #pragma unroll
        for (int j = 0; j < 8; j++) acc[i][j] = 0.f;

    const float* Ap = A + (long)(m0 + arow) * K + acol;
    const float* Bp = B + (long)brow * N + n0 + bcol;

    for (int k0 = 0; k0 < K; k0 += BK) {
        float4 a0 = *(const float4*)&Ap[k0];
        float4 a1 = *(const float4*)&Ap[k0 + 4];
        As[acol + 0][arow] = a0.x;  As[acol + 1][arow] = a0.y;
        As[acol + 2][arow] = a0.z;  As[acol + 3][arow] = a0.w;
        As[acol + 4][arow] = a1.x;  As[acol + 5][arow] = a1.y;
        As[acol + 6][arow] = a1.z;  As[acol + 7][arow] = a1.w;

        const float* bp = Bp + (long)k0 * N;
        *(float4*)&Bs[brow][bcol]     = *(const float4*)&bp[0];
        *(float4*)&Bs[brow][bcol + 4] = *(const float4*)&bp[4];
        __syncthreads();

        #pragma unroll
        for (int kk = 0; kk < BK; kk++) {
            float4 xa0 = *(const float4*)&As[kk][ty * 8];
            float4 xa1 = *(const float4*)&As[kk][ty * 8 + 4];
            float4 xb0 = *(const float4*)&Bs[kk][tx * 8];
            float4 xb1 = *(const float4*)&Bs[kk][tx * 8 + 4];
            float av[8] = {xa0.x, xa0.y, xa0.z, xa0.w, xa1.x, xa1.y, xa1.z, xa1.w};
            float bv[8] = {xb0.x, xb0.y, xb0.z, xb0.w, xb1.x, xb1.y, xb1.z, xb1.w};
            #pragma unroll
            for (int i = 0; i < 8; i++)
                #pragma unroll
                for (int j = 0; j < 8; j++)
                    acc[i][j] += av[i] * bv[j];
        }
        __syncthreads();
    }

    // epilogue
    #pragma unroll
    for (int i = 0; i < 8; i++) {
        int m = m0 + ty * 8 + i;
        #pragma unroll
        for (int j4 = 0; j4 < 2; j4++) {
            int n = n0 + tx * 8 + j4 * 4;
            float4 vo;
            vo.x = acc[i][j4 * 4 + 0];
            vo.y = acc[i][j4 * 4 + 1];
            vo.z = acc[i][j4 * 4 + 2];
            vo.w = acc[i][j4 * 4 + 3];
            if (bias) {
                float4 bb = *(const float4*)&bias[n];
                vo.x += bb.x; vo.y += bb.y; vo.z += bb.z; vo.w += bb.w;
            }
            if (mode == 0) {
                *(float4*)&C[(long)m * N + n] = vo;
            } else if (mode == 1) {
                float4 rr = *(const float4*)&res[(long)m * N + n];
                vo.x += rr.x; vo.y += rr.y; vo.z += rr.z; vo.w += rr.w;
                *(float4*)&C[(long)m * N + n] = vo;
            } else {
                // mode 2: expert scatter + residual
                int b  = m >> 8;        // local row in [0,1024): b*256 + j
                int jj = m & 255;
                long grow = ((long)b << 10) + (jj << 2) + z;
                long idx  = grow * HDIM + n;
                float4 rr = *(const float4*)&res[idx];
                vo.x += rr.x; vo.y += rr.y; vo.z += rr.z; vo.w += rr.w;
                *(float4*)&C[idx] = vo;
            }
        }
    }
}

// ---------------------------------------------------------------------------
// Flash attention: Br=128 q-rows, Bc=64 kv, d=64. 256 threads.
// thread(ty 0..15, tx 0..15): S rows ty*8..+8, cols tx*4..+4.
// ---------------------------------------------------------------------------
#define FBR 128
#define FBC 64
#define FST 68
#define FLASH_SMEM ((FBR + FBC + FBC + FBR) * FST * 4)

__global__ __launch_bounds__(256) void flash_kernel(
    const float* __restrict__ Q, const float* __restrict__ Kg,
    const float* __restrict__ Vg, float* __restrict__ O)
{
    extern __shared__ float sm[];
    float* Qs = sm;                    // [FBR][FST]  (pre-scaled Q)
    float* Kt = Qs + FBR * FST;        // [DHEAD][FST]   Kt[k][n]
    float* Vs = Kt + FBC * FST;        // [FBC][FST]     Vs[n][j]
    float* Ps = Vs + FBC * FST;        // [FBR][FST]

    const int tid = threadIdx.x;
    const int tx  = tid & 15;
    const int ty  = tid >> 4;
    const int q0  = blockIdx.x * FBR;
    const int h   = blockIdx.y;
    const int b   = blockIdx.z;
    const float scale = 0.125f;        // 1/sqrt(64)

    // Load Q tile (scaled)
    {
        int row = tid >> 1;
        int cb  = (tid & 1) * 32;
        const float* qg = Q + ((long)(b * NQ + q0 + row) << 10) + h * DHEAD + cb;
        #pragma unroll
        for (int ii = 0; ii < 8; ii++) {
            float4 t = *(const float4*)&qg[ii * 4];
            t.x *= scale; t.y *= scale; t.z *= scale; t.w *= scale;
            *(float4*)&Qs[row * FST + cb + ii * 4] = t;
        }
    }

    float m_i[8], l_i[8], o_acc[8][4];
    #pragma unroll
    for (int i = 0; i < 8; i++) {
        m_i[i] = -1e30f; l_i[i] = 0.f;
        o_acc[i][0] = o_acc[i][1] = o_acc[i][2] = o_acc[i][3] = 0.f;
    }
    __syncthreads();

    for (int n0 = 0; n0 < NKV; n0 += FBC) {
        // Load K (transposed) and V
        {
            int n  = tid >> 2;
            int kq = (tid & 3) * 16;
            const float* kg = Kg + ((long)(b * NKV + n0 + n) << 10) + h * DHEAD + kq;
            const float* vg = Vg + ((long)(b * NKV + n0 + n) << 10) + h * DHEAD + kq;
            #pragma unroll
            for (int ii = 0; ii < 4; ii++) {
                float4 kv4 = *(const float4*)&kg[ii * 4];
                int k = kq + ii * 4;
                Kt[(k + 0) * FST + n] = kv4.x;
                Kt[(k + 1) * FST + n] = kv4.y;
                Kt[(k + 2) * FST + n] = kv4.z;
                Kt[(k + 3) * FST + n] = kv4.w;
                *(float4*)&Vs[n * FST + kq + ii * 4] = *(const float4*)&vg[ii * 4];
            }
        }
        __syncthreads();

        // S = Qs @ K^T
        float s[8][4];
        #pragma unroll
        for (int i = 0; i < 8; i++)
            s[i][0] = s[i][1] = s[i][2] = s[i][3] = 0.f;
        #pragma unroll 4
        for (int k = 0; k < DHEAD; k++) {
            float4 bk = *(const float4*)&Kt[k * FST + tx * 4];
            #pragma unroll
            for (int i = 0; i < 8; i++) {
                float a = Qs[(ty * 8 + i) * FST + k];
                s[i][0] += a * bk.x; s[i][1] += a * bk.y;
                s[i][2] += a * bk.z; s[i][3] += a * bk.w;
            }
        }

        // online softmax per row
        #pragma unroll
        for (int i = 0; i < 8; i++) {
            float mx = fmaxf(fmaxf(s[i][0], s[i][1]), fmaxf(s[i][2], s[i][3]));
            #pragma unroll
            for (int off = 8; off; off >>= 1)
                mx = fmaxf(mx, __shfl_xor_sync(0xffffffffu, mx, off));
            float mnew  = fmaxf(m_i[i], mx);
            float alpha = __expf(m_i[i] - mnew);
            m_i[i] = mnew;
            float ls = 0.f;
            #pragma unroll
            for (int j = 0; j < 4; j++) {
                float p = __expf(s[i][j] - mnew);
                s[i][j] = p; ls += p;
            }
            #pragma unroll
            for (int off = 8; off; off >>= 1)
                ls += __shfl_xor_sync(0xffffffffu, ls, off);
            l_i[i] = l_i[i] * alpha + ls;
            o_acc[i][0] *= alpha; o_acc[i][1] *= alpha;
            o_acc[i][2] *= alpha; o_acc[i][3] *= alpha;
            float4 pw; pw.x = s[i][0]; pw.y = s[i][1]; pw.z = s[i][2]; pw.w = s[i][3];
            *(float4*)&Ps[(ty * 8 + i) * FST + tx * 4] = pw;
        }
        __syncwarp();   // P rows are produced/consumed within one warp

        // O += P @ V
        #pragma unroll 4
        for (int n = 0; n < FBC; n++) {
            float4 bv = *(const float4*)&Vs[n * FST + tx * 4];
            #pragma unroll
            for (int i = 0; i < 8; i++) {
                float p = Ps[(ty * 8 + i) * FST + n];
                o_acc[i][0] += p * bv.x; o_acc[i][1] += p * bv.y;
                o_acc[i][2] += p * bv.z; o_acc[i][3] += p * bv.w;
            }
        }
        __syncthreads();
    }

    // write ctx
    #pragma unroll
    for (int i = 0; i < 8; i++) {
        float inv = 1.0f / l_i[i];
        int r = q0 + ty * 8 + i;
        float4 ov;
        ov.x = o_acc[i][0] * inv; ov.y = o_acc[i][1] * inv;
        ov.z = o_acc[i][2] * inv; ov.w = o_acc[i][3] * inv;
        *(float4*)&O[((long)(b * NQ + r) << 10) + h * DHEAD + tx * 4] = ov;
    }
}

// ---------------------------------------------------------------------------
// SiLU(gate) * up
// ---------------------------------------------------------------------------
__global__ __launch_bounds__(256) void silu_kernel(
    const float* __restrict__ gu, float* __restrict__ inter)
{
    int idx = blockIdx.x * blockDim.x + threadIdx.x;   // float4 index, 1M total
    int t  = idx >> 8;
    int c4 = idx & 255;
    float4 g = *(const float4*)&gu[(long)t * (2 * IDIM) + c4 * 4];
    float4 u = *(const float4*)&gu[(long)t * (2 * IDIM) + IDIM + c4 * 4];
    float4 o;
    o.x = g.x / (1.f + __expf(-g.x)) * u.x;
    o.y = g.y / (1.f + __expf(-g.y)) * u.y;
    o.z = g.z / (1.f + __expf(-g.z)) * u.z;
    o.w = g.w / (1.f + __expf(-g.w)) * u.w;
    *(float4*)&inter[(long)t * IDIM + c4 * 4] = o;
}

// ---------------------------------------------------------------------------
// Launch
// ---------------------------------------------------------------------------
extern "C" void kernel_launch(void* const* d_in, const int* in_sizes, int n_in,
                              void* d_out, int out_size)
{
    const float* query     = (const float*)d_in[0];
    const float* key_value = (const float*)d_in[1];
    const float* Wq = (const float*)d_in[2];
    const float* bq = (const float*)d_in[3];
    const float* Wk = (const float*)d_in[4];
    const float* bk = (const float*)d_in[5];
    const float* Wv = (const float*)d_in[6];
    const float* bv = (const float*)d_in[7];
    const float* Wo = (const float*)d_in[8];
    const float* bo = (const float*)d_in[9];
    const float* g1 = (const float*)d_in[10];
    const float* b1 = (const float*)d_in[11];
    const float* g2 = (const float*)d_in[12];
    const float* b2 = (const float*)d_in[13];
    const float* gate_up = (const float*)d_in[14];
    const float* down    = (const float*)d_in[15];
    float* out = (float*)d_out;

    float *xln, *qb, *kb, *vb, *ctx, *res, *he, *gu, *inter;
    cudaGetSymbolAddress((void**)&xln,   g_xln);
    cudaGetSymbolAddress((void**)&qb,    g_q);
    cudaGetSymbolAddress((void**)&kb,    g_k);
    cudaGetSymbolAddress((void**)&vb,    g_v);
    cudaGetSymbolAddress((void**)&ctx,   g_ctx);
    cudaGetSymbolAddress((void**)&res,   g_res);
    cudaGetSymbolAddress((void**)&he,    g_he);
    cudaGetSymbolAddress((void**)&gu,    g_gu);
    cudaGetSymbolAddress((void**)&inter, g_int);

    cudaFuncSetAttribute(flash_kernel,
        cudaFuncAttributeMaxDynamicSharedMemorySize, FLASH_SMEM);

    // 1. LN1
    ln_kernel<<<BATCH * NQ, 256>>>(query, g1, b1, xln, 0);

    // 2-4. Q/K/V projections
    sgemm_kernel<<<dim3(8, 32), 256>>>(xln,       Wq, bq, nullptr, qb,
                                       BATCH * NQ, HDIM, HDIM, 0, 0, 0, 0);
    sgemm_kernel<<<dim3(8, 64), 256>>>(key_value, Wk, bk, nullptr, kb,
                                       BATCH * NKV, HDIM, HDIM, 0, 0, 0, 0);
    sgemm_kernel<<<dim3(8, 64), 256>>>(key_value, Wv, bv, nullptr, vb,
                                       BATCH * NKV, HDIM, HDIM, 0, 0, 0, 0);

    // 5. attention
    flash_kernel<<<dim3(NQ / FBR, NH, BATCH), 256, FLASH_SMEM>>>(qb, kb, vb, ctx);

    // 6. O proj + residual -> res
    sgemm_kernel<<<dim3(8, 32), 256>>>(ctx, Wo, bo, query, res,
                                       BATCH * NQ, HDIM, HDIM, 1, 0, 0, 0);

    // 7. LN2 with expert-grouped scatter -> he
    ln_kernel<<<BATCH * NQ, 256>>>(res, g2, b2, he, 1);

    // 8. gate_up GEMM (per expert, grid.z)
    sgemm_kernel<<<dim3(16, 8, NEXP), 256>>>(he, gate_up, nullptr, nullptr, gu,
                                             BATCH * NQ / NEXP, 2 * IDIM, HDIM, 0,
                                             (long)(BATCH * NQ / NEXP) * HDIM,
                                             (long)HDIM * 2 * IDIM,
                                             (long)(BATCH * NQ / NEXP) * 2 * IDIM);

    // 9. SiLU * up
    silu_kernel<<<(BATCH * NQ * IDIM / 4) / 256, 256>>>(gu, inter);

    // 10. down GEMM, scatter + residual -> out
    sgemm_kernel<<<dim3(8, 8, NEXP), 256>>>(inter, down, nullptr, res, out,
                                            BATCH * NQ / NEXP, HDIM, HDIM, 2,
                                            (long)(BATCH * NQ / NEXP) * HDIM,
                                            (long)HDIM * HDIM, 0);
}

// round 3
// speedup vs baseline: 1.6860x; 1.6860x over previous
#include <cuda_runtime.h>
#include <cuda_bf16.h>
#include <math.h>
#include <stdint.h>

// Problem constants
#define BATCH 4
#define NQ    1024
#define NKV   2048
#define HDIM  1024
#define NH    16
#define DHEAD 64
#define NEXP  4
#define IDIM  1024   // H*4/E

// ---------------------------------------------------------------------------
// Scratch (device globals — no allocations allowed)
// ---------------------------------------------------------------------------
__device__ float g_xln  [BATCH*NQ*HDIM];
__device__ float g_q    [BATCH*NQ*HDIM];
__device__ float g_k    [BATCH*NKV*HDIM];
__device__ float g_v    [BATCH*NKV*HDIM];
__device__ float g_ctx  [BATCH*NQ*HDIM];
__device__ float g_res  [BATCH*NQ*HDIM];
__device__ float g_he   [BATCH*NQ*HDIM];
__device__ float g_gu   [BATCH*NQ*2*IDIM];
__device__ float g_int  [BATCH*NQ*IDIM];
// transposed weights ([N][K], K contiguous)
__device__ float g_wqt  [HDIM*HDIM];
__device__ float g_wkt  [HDIM*HDIM];
__device__ float g_wvt  [HDIM*HDIM];
__device__ float g_wot  [HDIM*HDIM];
__device__ float g_gut  [NEXP*2*IDIM*HDIM];
__device__ float g_dnt  [NEXP*HDIM*IDIM];

// ---------------------------------------------------------------------------
// helpers
// ---------------------------------------------------------------------------
__device__ __forceinline__ uint32_t smem_u32(const void* p) {
    uint32_t a;
    asm("{ .reg .u64 t; cvta.to.shared.u64 t, %1; cvt.u32.u64 %0, t; }"
        : "=r"(a) : "l"(p));
    return a;
}

__device__ __forceinline__ void cp_async16(uint32_t saddr, const void* g) {
    asm volatile("cp.async.cg.shared.global [%0], [%1], 16;\n" :: "r"(saddr), "l"(g));
}

__device__ __forceinline__ uint32_t f2tf32(float f) {
    uint32_t r;
    asm("cvt.rna.tf32.f32 %0, %1;" : "=r"(r) : "f"(f));
    return r;
}

// mma.sync m16n8k8 tf32 (sm_80+, no arch-specific feature needed)
__device__ __forceinline__ void mma_tf32(float* c, const uint32_t* a, const uint32_t* b) {
    asm volatile(
        "mma.sync.aligned.m16n8k8.row.col.f32.tf32.tf32.f32 "
        "{%0,%1,%2,%3}, {%4,%5,%6,%7}, {%8,%9}, {%0,%1,%2,%3};"
        : "+f"(c[0]), "+f"(c[1]), "+f"(c[2]), "+f"(c[3])
        : "r"(a[0]), "r"(a[1]), "r"(a[2]), "r"(a[3]), "r"(b[0]), "r"(b[1]));
}

// ---------------------------------------------------------------------------
// Weight transpose: in[K][N] (N contiguous) -> out[N][K] (K contiguous)
// ---------------------------------------------------------------------------
__global__ __launch_bounds__(256) void transpose_kernel(
    const float* __restrict__ in, float* __restrict__ out, int K, int N)
{
    __shared__ float t[32][33];
    long zoff = (long)blockIdx.z * K * N;
    in  += zoff;
    out += zoff;
    int n0 = blockIdx.x * 32, k0 = blockIdx.y * 32;
    int tx = threadIdx.x & 31, ty = threadIdx.x >> 5;
    #pragma unroll
    for (int i = 0; i < 32; i += 8)
        t[ty + i][tx] = in[(long)(k0 + ty + i) * N + n0 + tx];
    __syncthreads();
    #pragma unroll
    for (int i = 0; i < 32; i += 8)
        out[(long)(n0 + ty + i) * K + k0 + tx] = t[tx][ty + i];
}

// ---------------------------------------------------------------------------
// tf32 mma.sync GEMM: C[M,N] = A[M,1024] @ Bt[N,1024]^T (+bias) + epilogue
//   mode 0: C = AB + bias
//   mode 1: C = AB + bias + res
//   mode 2: (MoE down scatter) grow = b*1024 + 4*j + e; C[grow*H+n] = res[..] + AB
// K hardcoded = 1024. Tile 128x128, 8 warps (each 64x32), K-chunk 16,
// double-buffered cp.async, smem stride 20 floats (bank-conflict-free frags).
// ---------------------------------------------------------------------------
#define GK 1024
#define NCHUNK (GK / 16)
#define BUF_FLOATS 5120            // (128*20)*2 matrices
#define GM_SMEM (2 * BUF_FLOATS * 4)

__device__ __forceinline__ void gl_load(
    const float* A, const float* Bt, int m0, int n0, int kc,
    uint32_t sbase, int buf, int tid)
{
    uint32_t abase = sbase + buf * (BUF_FLOATS * 4);
    uint32_t bbase = abase + 10240;
    const float* ag = A  + (long)m0 * GK + kc * 16;
    const float* bg = Bt + (long)n0 * GK + kc * 16;
    #pragma unroll
    for (int i = 0; i < 2; i++) {
        int idx = i * 256 + tid;           // 0..511
        int row = idx >> 2, c = idx & 3;
        uint32_t off = (uint32_t)(row * 80 + c * 16);
        cp_async16(abase + off, ag + (long)row * GK + c * 4);
        cp_async16(bbase + off, bg + (long)row * GK + c * 4);
    }
    asm volatile("cp.async.commit_group;\n" ::: "memory");
}

__global__ __launch_bounds__(256) void tc_gemm_kernel(
    const float* __restrict__ A, const float* __restrict__ Bt,
    const float* __restrict__ bias, const float* __restrict__ res,
    float* __restrict__ C, int M, int N, int mode,
    long sA, long sB, long sC)
{
    extern __shared__ __align__(16) float smem[];
    const int tid = threadIdx.x;
    const int z = blockIdx.z;
    A  += (long)z * sA;
    Bt += (long)z * sB;
    C  += (long)z * sC;
    const int m0 = blockIdx.y * 128;
    const int n0 = blockIdx.x * 128;

    const int w    = tid >> 5;
    const int lane = tid & 31;
    const int wm   = w & 1;         // m half (64 rows)
    const int wn   = w >> 1;        // n quarter (32 cols)
    const int g    = lane >> 2;
    const int tig  = lane & 3;

    uint32_t sbase = smem_u32(smem);

    float acc[4][4][4];
    #pragma unroll
    for (int mt = 0; mt < 4; mt++)
        #pragma unroll
        for (int nt = 0; nt < 4; nt++)
            acc[mt][nt][0] = acc[mt][nt][1] = acc[mt][nt][2] = acc[mt][nt][3] = 0.f;

    gl_load(A, Bt, m0, n0, 0, sbase, 0, tid);

    #pragma unroll 1
    for (int kc = 0; kc < NCHUNK; kc++) {
        const int buf = kc & 1;
        asm volatile("cp.async.wait_group 0;\n" ::: "memory");
        __syncthreads();
        if (kc + 1 < NCHUNK)
            gl_load(A, Bt, m0, n0, kc + 1, sbase, buf ^ 1, tid);

        const float* Asb = smem + buf * BUF_FLOATS;
        const float* Bsb = Asb + 2560;

        #pragma unroll
        for (int ks = 0; ks < 16; ks += 8) {
            uint32_t af[4][4], bf[4][2];
            #pragma unroll
            for (int mt = 0; mt < 4; mt++) {
                int r = wm * 64 + mt * 16 + g;
                af[mt][0] = f2tf32(Asb[r * 20 + ks + tig]);
                af[mt][1] = f2tf32(Asb[(r + 8) * 20 + ks + tig]);
                af[mt][2] = f2tf32(Asb[r * 20 + ks + tig + 4]);
                af[mt][3] = f2tf32(Asb[(r + 8) * 20 + ks + tig + 4]);
            }
            #pragma unroll
            for (int nt = 0; nt < 4; nt++) {
                int n = wn * 32 + nt * 8 + g;
                bf[nt][0] = f2tf32(Bsb[n * 20 + ks + tig]);
                bf[nt][1] = f2tf32(Bsb[n * 20 + ks + tig + 4]);
            }
            #pragma unroll
            for (int mt = 0; mt < 4; mt++)
                #pragma unroll
                for (int nt = 0; nt < 4; nt++)
                    mma_tf32(acc[mt][nt], af[mt], bf[nt]);
        }
    }

    // epilogue
    #pragma unroll
    for (int mt = 0; mt < 4; mt++) {
        #pragma unroll
        for (int half = 0; half < 2; half++) {
            int row = m0 + wm * 64 + mt * 16 + g + half * 8;
            long rbase;
            if (mode == 2) {
                int b = row >> 8, jj = row & 255;
                rbase = (((long)b << 10) + (jj << 2) + z) * (long)HDIM;
            } else {
                rbase = (long)row * N;
            }
            #pragma unroll
            for (int nt = 0; nt < 4; nt++) {
                int col = n0 + wn * 32 + nt * 8 + tig * 2;
                float vx = acc[mt][nt][half * 2 + 0];
                float vy = acc[mt][nt][half * 2 + 1];
                if (bias) { vx += bias[col]; vy += bias[col + 1]; }
                if (mode >= 1) {
                    const float2 rr = *(const float2*)&res[rbase + col];
                    vx += rr.x; vy += rr.y;
                }
                float2 o; o.x = vx; o.y = vy;
                *(float2*)&C[rbase + col] = o;
            }
        }
    }
}

// ---------------------------------------------------------------------------
// LayerNorm (one block per row of 1024). scatter=1 writes expert-grouped rows.
// ---------------------------------------------------------------------------
__global__ __launch_bounds__(256) void ln_kernel(
    const float* __restrict__ x, const float* __restrict__ g,
    const float* __restrict__ be, float* __restrict__ out, int scatter)
{
    const int row = blockIdx.x;
    const int tid = threadIdx.x;
    const float* xr = x + (long)row * HDIM;

    float4 v = *(const float4*)&xr[tid * 4];
    float s  = v.x + v.y + v.z + v.w;
    float s2 = v.x*v.x + v.y*v.y + v.z*v.z + v.w*v.w;

    #pragma unroll
    for (int off = 16; off; off >>= 1) {
        s  += __shfl_xor_sync(0xffffffffu, s,  off);
        s2 += __shfl_xor_sync(0xffffffffu, s2, off);
    }
    __shared__ float rs[8], rs2[8];
    int w = tid >> 5, lane = tid & 31;
    if (lane == 0) { rs[w] = s; rs2[w] = s2; }
    __syncthreads();
    float tot = 0.f, tot2 = 0.f;
    #pragma unroll
    for (int i = 0; i < 8; i++) { tot += rs[i]; tot2 += rs2[i]; }

    float mu   = tot * (1.0f / HDIM);
    float var  = tot2 * (1.0f / HDIM) - mu * mu;
    float rstd = rsqrtf(var + 1e-6f);

    int orow = row;
    if (scatter) {
        int b = row >> 10, q = row & 1023;
        orow = (q & 3) * (BATCH * NQ / NEXP) + b * (NQ / NEXP) + (q >> 2);
    }
    float4 gv = *(const float4*)&g[tid * 4];
    float4 bv = *(const float4*)&be[tid * 4];
    float4 y;
    y.x = (v.x - mu) * rstd * gv.x + bv.x;
    y.y = (v.y - mu) * rstd * gv.y + bv.y;
    y.z = (v.z - mu) * rstd * gv.z + bv.z;
    y.w = (v.w - mu) * rstd * gv.w + bv.w;
    *(float4*)&out[(long)orow * HDIM + tid * 4] = y;
}

// ---------------------------------------------------------------------------
// Flash attention: Br=128 q-rows, Bc=64 kv, d=64. 256 threads.
// ---------------------------------------------------------------------------
#define FBR 128
#define FBC 64
#define FST 68
#define FLASH_SMEM ((FBR + FBC + FBC + FBR) * FST * 4)

__global__ __launch_bounds__(256) void flash_kernel(
    const float* __restrict__ Q, const float* __restrict__ Kg,
    const float* __restrict__ Vg, float* __restrict__ O)
{
    extern __shared__ float sm[];
    float* Qs = sm;
    float* Kt = Qs + FBR * FST;
    float* Vs = Kt + FBC * FST;
    float* Ps = Vs + FBC * FST;

    const int tid = threadIdx.x;
    const int tx  = tid & 15;
    const int ty  = tid >> 4;
    const int q0  = blockIdx.x * FBR;
    const int h   = blockIdx.y;
    const int b   = blockIdx.z;
    const float scale = 0.125f;

    {
        int row = tid >> 1;
        int cb  = (tid & 1) * 32;
        const float* qg = Q + ((long)(b * NQ + q0 + row) << 10) + h * DHEAD + cb;
        #pragma unroll
        for (int ii = 0; ii < 8; ii++) {
            float4 t = *(const float4*)&qg[ii * 4];
            t.x *= scale; t.y *= scale; t.z *= scale; t.w *= scale;
            *(float4*)&Qs[row * FST + cb + ii * 4] = t;
        }
    }

    float m_i[8], l_i[8], o_acc[8][4];
    #pragma unroll
    for (int i = 0; i < 8; i++) {
        m_i[i] = -1e30f; l_i[i] = 0.f;
        o_acc[i][0] = o_acc[i][1] = o_acc[i][2] = o_acc[i][3] = 0.f;
    }
    __syncthreads();

    for (int n0 = 0; n0 < NKV; n0 += FBC) {
        {
            int n  = tid >> 2;
            int kq = (tid & 3) * 16;
            const float* kg = Kg + ((long)(b * NKV + n0 + n) << 10) + h * DHEAD + kq;
            const float* vg = Vg + ((long)(b * NKV + n0 + n) << 10) + h * DHEAD + kq;
            #pragma unroll
            for (int ii = 0; ii < 4; ii++) {
                float4 kv4 = *(const float4*)&kg[ii * 4];
                int k = kq + ii * 4;
                Kt[(k + 0) * FST + n] = kv4.x;
                Kt[(k + 1) * FST + n] = kv4.y;
                Kt[(k + 2) * FST + n] = kv4.z;
                Kt[(k + 3) * FST + n] = kv4.w;
                *(float4*)&Vs[n * FST + kq + ii * 4] = *(const float4*)&vg[ii * 4];
            }
        }
        __syncthreads();

        float s[8][4];
        #pragma unroll
        for (int i = 0; i < 8; i++)
            s[i][0] = s[i][1] = s[i][2] = s[i][3] = 0.f;
        #pragma unroll 4
        for (int k = 0; k < DHEAD; k++) {
            float4 bk = *(const float4*)&Kt[k * FST + tx * 4];
            #pragma unroll
            for (int i = 0; i < 8; i++) {
                float a = Qs[(ty * 8 + i) * FST + k];
                s[i][0] += a * bk.x; s[i][1] += a * bk.y;
                s[i][2] += a * bk.z; s[i][3] += a * bk.w;
            }
        }

        #pragma unroll
        for (int i = 0; i < 8; i++) {
            float mx = fmaxf(fmaxf(s[i][0], s[i][1]), fmaxf(s[i][2], s[i][3]));
            #pragma unroll
            for (int off = 8; off; off >>= 1)
                mx = fmaxf(mx, __shfl_xor_sync(0xffffffffu, mx, off));
            float mnew  = fmaxf(m_i[i], mx);
            float alpha = __expf(m_i[i] - mnew);
            m_i[i] = mnew;
            float ls = 0.f;
            #pragma unroll
            for (int j = 0; j < 4; j++) {
                float p = __expf(s[i][j] - mnew);
                s[i][j] = p; ls += p;
            }
            #pragma unroll
            for (int off = 8; off; off >>= 1)
                ls += __shfl_xor_sync(0xffffffffu, ls, off);
            l_i[i] = l_i[i] * alpha + ls;
            o_acc[i][0] *= alpha; o_acc[i][1] *= alpha;
            o_acc[i][2] *= alpha; o_acc[i][3] *= alpha;
            float4 pw; pw.x = s[i][0]; pw.y = s[i][1]; pw.z = s[i][2]; pw.w = s[i][3];
            *(float4*)&Ps[(ty * 8 + i) * FST + tx * 4] = pw;
        }
        __syncwarp();

        #pragma unroll 4
        for (int n = 0; n < FBC; n++) {
            float4 bv = *(const float4*)&Vs[n * FST + tx * 4];
            #pragma unroll
            for (int i = 0; i < 8; i++) {
                float p = Ps[(ty * 8 + i) * FST + n];
                o_acc[i][0] += p * bv.x; o_acc[i][1] += p * bv.y;
                o_acc[i][2] += p * bv.z; o_acc[i][3] += p * bv.w;
            }
        }
        __syncthreads();
    }

    #pragma unroll
    for (int i = 0; i < 8; i++) {
        float inv = 1.0f / l_i[i];
        int r = q0 + ty * 8 + i;
        float4 ov;
        ov.x = o_acc[i][0] * inv; ov.y = o_acc[i][1] * inv;
        ov.z = o_acc[i][2] * inv; ov.w = o_acc[i][3] * inv;
        *(float4*)&O[((long)(b * NQ + r) << 10) + h * DHEAD + tx * 4] = ov;
    }
}

// ---------------------------------------------------------------------------
// SiLU(gate) * up
// ---------------------------------------------------------------------------
__global__ __launch_bounds__(256) void silu_kernel(
    const float* __restrict__ gu, float* __restrict__ inter)
{
    int idx = blockIdx.x * blockDim.x + threadIdx.x;
    int t  = idx >> 8;
    int c4 = idx & 255;
    float4 g = *(const float4*)&gu[(long)t * (2 * IDIM) + c4 * 4];
    float4 u = *(const float4*)&gu[(long)t * (2 * IDIM) + IDIM + c4 * 4];
    float4 o;
    o.x = g.x / (1.f + __expf(-g.x)) * u.x;
    o.y = g.y / (1.f + __expf(-g.y)) * u.y;
    o.z = g.z / (1.f + __expf(-g.z)) * u.z;
    o.w = g.w / (1.f + __expf(-g.w)) * u.w;
    *(float4*)&inter[(long)t * IDIM + c4 * 4] = o;
}

// ---------------------------------------------------------------------------
// Launch
// ---------------------------------------------------------------------------
extern "C" void kernel_launch(void* const* d_in, const int* in_sizes, int n_in,
                              void* d_out, int out_size)
{
    const float* query     = (const float*)d_in[0];
    const float* key_value = (const float*)d_in[1];
    const float* Wq = (const float*)d_in[2];
    const float* bq = (const float*)d_in[3];
    const float* Wk = (const float*)d_in[4];
    const float* bk = (const float*)d_in[5];
    const float* Wv = (const float*)d_in[6];
    const float* bv = (const float*)d_in[7];
    const float* Wo = (const float*)d_in[8];
    const float* bo = (const float*)d_in[9];
    const float* g1 = (const float*)d_in[10];
    const float* b1 = (const float*)d_in[11];
    const float* g2 = (const float*)d_in[12];
    const float* b2 = (const float*)d_in[13];
    const float* gate_up = (const float*)d_in[14];
    const float* down    = (const float*)d_in[15];
    float* out = (float*)d_out;

    float *xln, *qb, *kb, *vb, *ctx, *res, *he, *gu, *inter;
    float *wqt, *wkt, *wvt, *wot, *gut, *dnt;
    cudaGetSymbolAddress((void**)&xln,   g_xln);
    cudaGetSymbolAddress((void**)&qb,    g_q);
    cudaGetSymbolAddress((void**)&kb,    g_k);
    cudaGetSymbolAddress((void**)&vb,    g_v);
    cudaGetSymbolAddress((void**)&ctx,   g_ctx);
    cudaGetSymbolAddress((void**)&res,   g_res);
    cudaGetSymbolAddress((void**)&he,    g_he);
    cudaGetSymbolAddress((void**)&gu,    g_gu);
    cudaGetSymbolAddress((void**)&inter, g_int);
    cudaGetSymbolAddress((void**)&wqt,   g_wqt);
    cudaGetSymbolAddress((void**)&wkt,   g_wkt);
    cudaGetSymbolAddress((void**)&wvt,   g_wvt);
    cudaGetSymbolAddress((void**)&wot,   g_wot);
    cudaGetSymbolAddress((void**)&gut,   g_gut);
    cudaGetSymbolAddress((void**)&dnt,   g_dnt);

    cudaFuncSetAttribute(flash_kernel,
        cudaFuncAttributeMaxDynamicSharedMemorySize, FLASH_SMEM);
    cudaFuncSetAttribute(tc_gemm_kernel,
        cudaFuncAttributeMaxDynamicSharedMemorySize, GM_SMEM);

    // 0. weight transposes ([K,N] -> [N,K])
    transpose_kernel<<<dim3(32, 32), 256>>>(Wq, wqt, HDIM, HDIM);
    transpose_kernel<<<dim3(32, 32), 256>>>(Wk, wkt, HDIM, HDIM);
    transpose_kernel<<<dim3(32, 32), 256>>>(Wv, wvt, HDIM, HDIM);
    transpose_kernel<<<dim3(32, 32), 256>>>(Wo, wot, HDIM, HDIM);
    transpose_kernel<<<dim3(64, 32, NEXP), 256>>>(gate_up, gut, HDIM, 2 * IDIM);
    transpose_kernel<<<dim3(32, 32, NEXP), 256>>>(down, dnt, IDIM, HDIM);

    // 1. LN1
    ln_kernel<<<BATCH * NQ, 256>>>(query, g1, b1, xln, 0);

    // 2-4. Q/K/V projections (tf32 mma.sync tensor cores)
    tc_gemm_kernel<<<dim3(8, 32), 256, GM_SMEM>>>(xln, wqt, bq, nullptr, qb,
                                                  BATCH * NQ, HDIM, 0, 0, 0, 0);
    tc_gemm_kernel<<<dim3(8, 64), 256, GM_SMEM>>>(key_value, wkt, bk, nullptr, kb,
                                                  BATCH * NKV, HDIM, 0, 0, 0, 0);
    tc_gemm_kernel<<<dim3(8, 64), 256, GM_SMEM>>>(key_value, wvt, bv, nullptr, vb,
                                                  BATCH * NKV, HDIM, 0, 0, 0, 0);

    // 5. attention
    flash_kernel<<<dim3(NQ / FBR, NH, BATCH), 256, FLASH_SMEM>>>(qb, kb, vb, ctx);

    // 6. O proj + residual -> res
    tc_gemm_kernel<<<dim3(8, 32), 256, GM_SMEM>>>(ctx, wot, bo, query, res,
                                                  BATCH * NQ, HDIM, 1, 0, 0, 0);

    // 7. LN2 with expert-grouped scatter -> he
    ln_kernel<<<BATCH * NQ, 256>>>(res, g2, b2, he, 1);

    // 8. gate_up GEMM (per expert)
    tc_gemm_kernel<<<dim3(16, 8, NEXP), 256, GM_SMEM>>>(he, gut, nullptr, nullptr, gu,
        BATCH * NQ / NEXP, 2 * IDIM, 0,
        (long)(BATCH * NQ / NEXP) * HDIM,
        (long)2 * IDIM * HDIM,
        (long)(BATCH * NQ / NEXP) * 2 * IDIM);

    // 9. SiLU * up
    silu_kernel<<<(BATCH * NQ * IDIM / 4) / 256, 256>>>(gu, inter);

    // 10. down GEMM, scatter + residual -> out
    tc_gemm_kernel<<<dim3(8, 8, NEXP), 256, GM_SMEM>>>(inter, dnt, nullptr, res, out,
        BATCH * NQ / NEXP, HDIM, 2,
        (long)(BATCH * NQ / NEXP) * IDIM,
        (long)HDIM * IDIM, 0);
}

// round 4
// speedup vs baseline: 2.6781x; 1.5884x over previous
#include <cuda_runtime.h>
#include <cuda_bf16.h>
#include <math.h>
#include <stdint.h>

// Problem constants
#define BATCH 4
#define NQ    1024
#define NKV   2048
#define HDIM  1024
#define NH    16
#define DHEAD 64
#define NEXP  4
#define IDIM  1024   // H*4/E

// ---------------------------------------------------------------------------
// Scratch (device globals — no allocations allowed)
// ---------------------------------------------------------------------------
__device__ float g_xln  [BATCH*NQ*HDIM];
__device__ float g_q    [BATCH*NQ*HDIM];
__device__ float g_k    [BATCH*NKV*HDIM];
__device__ float g_v    [BATCH*NKV*HDIM];
__device__ float g_ctx  [BATCH*NQ*HDIM];
__device__ float g_res  [BATCH*NQ*HDIM];
__device__ float g_he   [BATCH*NQ*HDIM];
__device__ float g_gu   [BATCH*NQ*2*IDIM];
__device__ float g_int  [BATCH*NQ*IDIM];
// transposed weights ([N][K], K contiguous)
__device__ float g_wqt  [HDIM*HDIM];
__device__ float g_wkt  [HDIM*HDIM];
__device__ float g_wvt  [HDIM*HDIM];
__device__ float g_wot  [HDIM*HDIM];
__device__ float g_gut  [NEXP*2*IDIM*HDIM];
__device__ float g_dnt  [NEXP*HDIM*IDIM];

// ---------------------------------------------------------------------------
// helpers
// ---------------------------------------------------------------------------
__device__ __forceinline__ uint32_t smem_u32(const void* p) {
    uint32_t a;
    asm("{ .reg .u64 t; cvta.to.shared.u64 t, %1; cvt.u32.u64 %0, t; }"
        : "=r"(a) : "l"(p));
    return a;
}

__device__ __forceinline__ void cp_async16(uint32_t saddr, const void* g) {
    asm volatile("cp.async.cg.shared.global [%0], [%1], 16;\n" :: "r"(saddr), "l"(g));
}

__device__ __forceinline__ uint32_t f2tf32(float f) {
    uint32_t r;
    asm("cvt.rna.tf32.f32 %0, %1;" : "=r"(r) : "f"(f));
    return r;
}

__device__ __forceinline__ float ex2(float x) {
    float r;
    asm("ex2.approx.ftz.f32 %0, %1;" : "=f"(r) : "f"(x));
    return r;
}

// mma.sync m16n8k8 tf32 (sm_80+, no arch-specific feature needed)
__device__ __forceinline__ void mma_tf32(float* c, const uint32_t* a, const uint32_t* b) {
    asm volatile(
        "mma.sync.aligned.m16n8k8.row.col.f32.tf32.tf32.f32 "
        "{%0,%1,%2,%3}, {%4,%5,%6,%7}, {%8,%9}, {%0,%1,%2,%3};"
        : "+f"(c[0]), "+f"(c[1]), "+f"(c[2]), "+f"(c[3])
        : "r"(a[0]), "r"(a[1]), "r"(a[2]), "r"(a[3]), "r"(b[0]), "r"(b[1]));
}

// ---------------------------------------------------------------------------
// Weight transpose: in[K][N] (N contiguous) -> out[N][K] (K contiguous)
// ---------------------------------------------------------------------------
__global__ __launch_bounds__(256) void transpose_kernel(
    const float* __restrict__ in, float* __restrict__ out, int K, int N)
{
    __shared__ float t[32][33];
    long zoff = (long)blockIdx.z * K * N;
    in  += zoff;
    out += zoff;
    int n0 = blockIdx.x * 32, k0 = blockIdx.y * 32;
    int tx = threadIdx.x & 31, ty = threadIdx.x >> 5;
    #pragma unroll
    for (int i = 0; i < 32; i += 8)
        t[ty + i][tx] = in[(long)(k0 + ty + i) * N + n0 + tx];
    __syncthreads();
    #pragma unroll
    for (int i = 0; i < 32; i += 8)
        out[(long)(n0 + ty + i) * K + k0 + tx] = t[tx][ty + i];
}

// ---------------------------------------------------------------------------
// tf32 mma.sync GEMM (unchanged from R3): C = A @ Bt^T (+bias) + epilogue
// ---------------------------------------------------------------------------
#define GK 1024
#define NCHUNK (GK / 16)
#define BUF_FLOATS 5120
#define GM_SMEM (2 * BUF_FLOATS * 4)

__device__ __forceinline__ void gl_load(
    const float* A, const float* Bt, int m0, int n0, int kc,
    uint32_t sbase, int buf, int tid)
{
    uint32_t abase = sbase + buf * (BUF_FLOATS * 4);
    uint32_t bbase = abase + 10240;
    const float* ag = A  + (long)m0 * GK + kc * 16;
    const float* bg = Bt + (long)n0 * GK + kc * 16;
    #pragma unroll
    for (int i = 0; i < 2; i++) {
        int idx = i * 256 + tid;
        int row = idx >> 2, c = idx & 3;
        uint32_t off = (uint32_t)(row * 80 + c * 16);
        cp_async16(abase + off, ag + (long)row * GK + c * 4);
        cp_async16(bbase + off, bg + (long)row * GK + c * 4);
    }
    asm volatile("cp.async.commit_group;\n" ::: "memory");
}

__global__ __launch_bounds__(256) void tc_gemm_kernel(
    const float* __restrict__ A, const float* __restrict__ Bt,
    const float* __restrict__ bias, const float* __restrict__ res,
    float* __restrict__ C, int M, int N, int mode,
    long sA, long sB, long sC)
{
    extern __shared__ __align__(16) float smem[];
    const int tid = threadIdx.x;
    const int z = blockIdx.z;
    A  += (long)z * sA;
    Bt += (long)z * sB;
    C  += (long)z * sC;
    const int m0 = blockIdx.y * 128;
    const int n0 = blockIdx.x * 128;

    const int w    = tid >> 5;
    const int lane = tid & 31;
    const int wm   = w & 1;
    const int wn   = w >> 1;
    const int g    = lane >> 2;
    const int tig  = lane & 3;

    uint32_t sbase = smem_u32(smem);

    float acc[4][4][4];
    #pragma unroll
    for (int mt = 0; mt < 4; mt++)
        #pragma unroll
        for (int nt = 0; nt < 4; nt++)
            acc[mt][nt][0] = acc[mt][nt][1] = acc[mt][nt][2] = acc[mt][nt][3] = 0.f;

    gl_load(A, Bt, m0, n0, 0, sbase, 0, tid);

    #pragma unroll 1
    for (int kc = 0; kc < NCHUNK; kc++) {
        const int buf = kc & 1;
        asm volatile("cp.async.wait_group 0;\n" ::: "memory");
        __syncthreads();
        if (kc + 1 < NCHUNK)
            gl_load(A, Bt, m0, n0, kc + 1, sbase, buf ^ 1, tid);

        const float* Asb = smem + buf * BUF_FLOATS;
        const float* Bsb = Asb + 2560;

        #pragma unroll
        for (int ks = 0; ks < 16; ks += 8) {
            uint32_t af[4][4], bf[4][2];
            #pragma unroll
            for (int mt = 0; mt < 4; mt++) {
                int r = wm * 64 + mt * 16 + g;
                af[mt][0] = f2tf32(Asb[r * 20 + ks + tig]);
                af[mt][1] = f2tf32(Asb[(r + 8) * 20 + ks + tig]);
                af[mt][2] = f2tf32(Asb[r * 20 + ks + tig + 4]);
                af[mt][3] = f2tf32(Asb[(r + 8) * 20 + ks + tig + 4]);
            }
            #pragma unroll
            for (int nt = 0; nt < 4; nt++) {
                int n = wn * 32 + nt * 8 + g;
                bf[nt][0] = f2tf32(Bsb[n * 20 + ks + tig]);
                bf[nt][1] = f2tf32(Bsb[n * 20 + ks + tig + 4]);
            }
            #pragma unroll
            for (int mt = 0; mt < 4; mt++)
                #pragma unroll
                for (int nt = 0; nt < 4; nt++)
                    mma_tf32(acc[mt][nt], af[mt], bf[nt]);
        }
    }

    #pragma unroll
    for (int mt = 0; mt < 4; mt++) {
        #pragma unroll
        for (int half = 0; half < 2; half++) {
            int row = m0 + wm * 64 + mt * 16 + g + half * 8;
            long rbase;
            if (mode == 2) {
                int b = row >> 8, jj = row & 255;
                rbase = (((long)b << 10) + (jj << 2) + z) * (long)HDIM;
            } else {
                rbase = (long)row * N;
            }
            #pragma unroll
            for (int nt = 0; nt < 4; nt++) {
                int col = n0 + wn * 32 + nt * 8 + tig * 2;
                float vx = acc[mt][nt][half * 2 + 0];
                float vy = acc[mt][nt][half * 2 + 1];
                if (bias) { vx += bias[col]; vy += bias[col + 1]; }
                if (mode >= 1) {
                    const float2 rr = *(const float2*)&res[rbase + col];
                    vx += rr.x; vy += rr.y;
                }
                float2 o; o.x = vx; o.y = vy;
                *(float2*)&C[rbase + col] = o;
            }
        }
    }
}

// ---------------------------------------------------------------------------
// LayerNorm (one block per row of 1024). scatter=1 writes expert-grouped rows.
// ---------------------------------------------------------------------------
__global__ __launch_bounds__(256) void ln_kernel(
    const float* __restrict__ x, const float* __restrict__ g,
    const float* __restrict__ be, float* __restrict__ out, int scatter)
{
    const int row = blockIdx.x;
    const int tid = threadIdx.x;
    const float* xr = x + (long)row * HDIM;

    float4 v = *(const float4*)&xr[tid * 4];
    float s  = v.x + v.y + v.z + v.w;
    float s2 = v.x*v.x + v.y*v.y + v.z*v.z + v.w*v.w;

    #pragma unroll
    for (int off = 16; off; off >>= 1) {
        s  += __shfl_xor_sync(0xffffffffu, s,  off);
        s2 += __shfl_xor_sync(0xffffffffu, s2, off);
    }
    __shared__ float rs[8], rs2[8];
    int w = tid >> 5, lane = tid & 31;
    if (lane == 0) { rs[w] = s; rs2[w] = s2; }
    __syncthreads();
    float tot = 0.f, tot2 = 0.f;
    #pragma unroll
    for (int i = 0; i < 8; i++) { tot += rs[i]; tot2 += rs2[i]; }

    float mu   = tot * (1.0f / HDIM);
    float var  = tot2 * (1.0f / HDIM) - mu * mu;
    float rstd = rsqrtf(var + 1e-6f);

    int orow = row;
    if (scatter) {
        int b = row >> 10, q = row & 1023;
        orow = (q & 3) * (BATCH * NQ / NEXP) + b * (NQ / NEXP) + (q >> 2);
    }
    float4 gv = *(const float4*)&g[tid * 4];
    float4 bv = *(const float4*)&be[tid * 4];
    float4 y;
    y.x = (v.x - mu) * rstd * gv.x + bv.x;
    y.y = (v.y - mu) * rstd * gv.y + bv.y;
    y.z = (v.z - mu) * rstd * gv.z + bv.z;
    y.w = (v.w - mu) * rstd * gv.w + bv.w;
    *(float4*)&out[(long)orow * HDIM + tid * 4] = y;
}

// ---------------------------------------------------------------------------
// Tensor-core flash attention (tf32 mma.sync).
// Br=128, Bc=64, d=64. 8 warps; warp w owns q-rows [w*16, w*16+16).
// Q pre-scaled by 0.125*log2(e), softmax uses ex2.
// ---------------------------------------------------------------------------
#define FLD 68
#define FK_OFF(b)  ((b) * (64 * FLD))
#define FV_OFF(b)  (2 * 64 * FLD + (b) * (64 * FLD))
#define FP_OFF     (4 * 64 * FLD)
#define FL_SMEM    ((4 * 64 * FLD + 128 * FLD) * 4)

__device__ __forceinline__ void fl_load_kv(
    const float* Kg, const float* Vg, int b, int h, int n0,
    uint32_t sbase, int buf, int tid)
{
    uint32_t kb = sbase + FK_OFF(buf) * 4;
    uint32_t vb = sbase + FV_OFF(buf) * 4;
    const float* kg = Kg + ((long)(b * NKV + n0) << 10) + h * DHEAD;
    const float* vg = Vg + ((long)(b * NKV + n0) << 10) + h * DHEAD;
    #pragma unroll
    for (int i = 0; i < 4; i++) {
        int idx = i * 256 + tid;          // 0..1023
        int row = idx >> 4, c = idx & 15;
        uint32_t off = (uint32_t)((row * FLD + c * 4) * 4);
        cp_async16(kb + off, kg + ((long)row << 10) + c * 4);
        cp_async16(vb + off, vg + ((long)row << 10) + c * 4);
    }
    asm volatile("cp.async.commit_group;\n" ::: "memory");
}

__global__ __launch_bounds__(256) void flash_kernel(
    const float* __restrict__ Q, const float* __restrict__ Kg,
    const float* __restrict__ Vg, float* __restrict__ O)
{
    extern __shared__ __align__(16) float sm[];
    const int tid  = threadIdx.x;
    const int w    = tid >> 5;
    const int lane = tid & 31;
    const int g    = lane >> 2;
    const int tig  = lane & 3;
    const int q0   = blockIdx.x * 128;
    const int h    = blockIdx.y;
    const int b    = blockIdx.z;
    const float QS = 0.125f * 1.44269504088896f;  // scale * log2(e)

    uint32_t sbase = smem_u32(sm);
    float* Pq = sm + FP_OFF;                // Q staging, then per-warp P

    // stage Q tile into Pq
    {
        uint32_t pb = sbase + FP_OFF * 4;
        const float* qg = Q + ((long)(b * NQ + q0) << 10) + h * DHEAD;
        #pragma unroll
        for (int i = 0; i < 8; i++) {
            int idx = i * 256 + tid;        // 0..2047
            int row = idx >> 4, c = idx & 15;
            cp_async16(pb + (uint32_t)((row * FLD + c * 4) * 4),
                       qg + ((long)row << 10) + c * 4);
        }
        asm volatile("cp.async.commit_group;\n" ::: "memory");
    }
    fl_load_kv(Kg, Vg, b, h, 0, sbase, 0, tid);
    asm volatile("cp.async.wait_group 0;\n" ::: "memory");
    __syncthreads();

    // extract Q fragments (warp-private rows; reuse of Pq as P is warp-local)
    uint32_t qf[8][4];
    {
        const float* qr = Pq + (w * 16) * FLD;
        #pragma unroll
        for (int s = 0; s < 8; s++) {
            qf[s][0] = f2tf32(qr[g * FLD + s * 8 + tig] * QS);
            qf[s][1] = f2tf32(qr[(g + 8) * FLD + s * 8 + tig] * QS);
            qf[s][2] = f2tf32(qr[g * FLD + s * 8 + tig + 4] * QS);
            qf[s][3] = f2tf32(qr[(g + 8) * FLD + s * 8 + tig + 4] * QS);
        }
    }
    __syncwarp();

    float m_lo = -1e30f, m_hi = -1e30f, l_lo = 0.f, l_hi = 0.f;
    float o[8][4];
    #pragma unroll
    for (int nt = 0; nt < 8; nt++)
        o[nt][0] = o[nt][1] = o[nt][2] = o[nt][3] = 0.f;

    uint32_t* Pw  = (uint32_t*)(Pq + (w * 16) * FLD);   // warp's P strip (tf32)

    #pragma unroll 1
    for (int kc = 0; kc < NKV / 64; kc++) {
        const int buf = kc & 1;
        if (kc + 1 < NKV / 64) {
            fl_load_kv(Kg, Vg, b, h, (kc + 1) * 64, sbase, buf ^ 1, tid);
            asm volatile("cp.async.wait_group 1;\n" ::: "memory");
        } else {
            asm volatile("cp.async.wait_group 0;\n" ::: "memory");
        }
        __syncthreads();

        const float* Ks = sm + FK_OFF(buf);
        const float* Vs = sm + FV_OFF(buf);

        // S = Q @ K^T  (in log2 domain)
        float sa[8][4];
        #pragma unroll
        for (int nt = 0; nt < 8; nt++) {
            sa[nt][0] = sa[nt][1] = sa[nt][2] = sa[nt][3] = 0.f;
            #pragma unroll
            for (int s = 0; s < 8; s++) {
                uint32_t bf[2];
                bf[0] = f2tf32(Ks[(nt * 8 + g) * FLD + s * 8 + tig]);
                bf[1] = f2tf32(Ks[(nt * 8 + g) * FLD + s * 8 + tig + 4]);
                mma_tf32(sa[nt], qf[s], bf);
            }
        }

        // online softmax
        float tmx_lo = sa[0][0], tmx_hi = sa[0][2];
        #pragma unroll
        for (int nt = 0; nt < 8; nt++) {
            tmx_lo = fmaxf(tmx_lo, fmaxf(sa[nt][0], sa[nt][1]));
            tmx_hi = fmaxf(tmx_hi, fmaxf(sa[nt][2], sa[nt][3]));
        }
        tmx_lo = fmaxf(tmx_lo, __shfl_xor_sync(0xffffffffu, tmx_lo, 1));
        tmx_lo = fmaxf(tmx_lo, __shfl_xor_sync(0xffffffffu, tmx_lo, 2));
        tmx_hi = fmaxf(tmx_hi, __shfl_xor_sync(0xffffffffu, tmx_hi, 1));
        tmx_hi = fmaxf(tmx_hi, __shfl_xor_sync(0xffffffffu, tmx_hi, 2));

        float mn_lo = fmaxf(m_lo, tmx_lo);
        float mn_hi = fmaxf(m_hi, tmx_hi);
        float al_lo = ex2(m_lo - mn_lo);
        float al_hi = ex2(m_hi - mn_hi);
        m_lo = mn_lo; m_hi = mn_hi;

        float rs_lo = 0.f, rs_hi = 0.f;
        #pragma unroll
        for (int nt = 0; nt < 8; nt++) {
            float p0 = ex2(sa[nt][0] - mn_lo);
            float p1 = ex2(sa[nt][1] - mn_lo);
            float p2 = ex2(sa[nt][2] - mn_hi);
            float p3 = ex2(sa[nt][3] - mn_hi);
            rs_lo += p0 + p1;
            rs_hi += p2 + p3;
            // store P (tf32) to warp strip
            uint2 lo; lo.x = f2tf32(p0); lo.y = f2tf32(p1);
            uint2 hi; hi.x = f2tf32(p2); hi.y = f2tf32(p3);
            *(uint2*)&Pw[g * FLD + nt * 8 + tig * 2]       = lo;
            *(uint2*)&Pw[(g + 8) * FLD + nt * 8 + tig * 2] = hi;
        }
        rs_lo += __shfl_xor_sync(0xffffffffu, rs_lo, 1);
        rs_lo += __shfl_xor_sync(0xffffffffu, rs_lo, 2);
        rs_hi += __shfl_xor_sync(0xffffffffu, rs_hi, 1);
        rs_hi += __shfl_xor_sync(0xffffffffu, rs_hi, 2);
        l_lo = l_lo * al_lo + rs_lo;
        l_hi = l_hi * al_hi + rs_hi;
        #pragma unroll
        for (int nt = 0; nt < 8; nt++) {
            o[nt][0] *= al_lo; o[nt][1] *= al_lo;
            o[nt][2] *= al_hi; o[nt][3] *= al_hi;
        }
        __syncwarp();

        // O += P @ V   (A from P strip, B = V read as col-major directly)
        #pragma unroll
        for (int s = 0; s < 8; s++) {
            uint32_t af[4];
            af[0] = Pw[g * FLD + s * 8 + tig];
            af[1] = Pw[(g + 8) * FLD + s * 8 + tig];
            af[2] = Pw[g * FLD + s * 8 + tig + 4];
            af[3] = Pw[(g + 8) * FLD + s * 8 + tig + 4];
            #pragma unroll
            for (int nt = 0; nt < 8; nt++) {
                uint32_t bf[2];
                bf[0] = f2tf32(Vs[(s * 8 + tig) * FLD + nt * 8 + g]);
                bf[1] = f2tf32(Vs[(s * 8 + tig + 4) * FLD + nt * 8 + g]);
                mma_tf32(o[nt], af, bf);
            }
        }
        __syncthreads();
    }

    // write ctx
    float il_lo = 1.0f / l_lo, il_hi = 1.0f / l_hi;
    int row_lo = q0 + w * 16 + g;
    int row_hi = row_lo + 8;
    #pragma unroll
    for (int nt = 0; nt < 8; nt++) {
        int col = h * DHEAD + nt * 8 + tig * 2;
        float2 vlo; vlo.x = o[nt][0] * il_lo; vlo.y = o[nt][1] * il_lo;
        float2 vhi; vhi.x = o[nt][2] * il_hi; vhi.y = o[nt][3] * il_hi;
        *(float2*)&O[((long)(b * NQ + row_lo) << 10) + col] = vlo;
        *(float2*)&O[((long)(b * NQ + row_hi) << 10) + col] = vhi;
    }
}

// ---------------------------------------------------------------------------
// SiLU(gate) * up
// ---------------------------------------------------------------------------
__global__ __launch_bounds__(256) void silu_kernel(
    const float* __restrict__ gu, float* __restrict__ inter)
{
    int idx = blockIdx.x * blockDim.x + threadIdx.x;
    int t  = idx >> 8;
    int c4 = idx & 255;
    float4 g = *(const float4*)&gu[(long)t * (2 * IDIM) + c4 * 4];
    float4 u = *(const float4*)&gu[(long)t * (2 * IDIM) + IDIM + c4 * 4];
    float4 o;
    o.x = g.x / (1.f + __expf(-g.x)) * u.x;
    o.y = g.y / (1.f + __expf(-g.y)) * u.y;
    o.z = g.z / (1.f + __expf(-g.z)) * u.z;
    o.w = g.w / (1.f + __expf(-g.w)) * u.w;
    *(float4*)&inter[(long)t * IDIM + c4 * 4] = o;
}

// ---------------------------------------------------------------------------
// Launch
// ---------------------------------------------------------------------------
extern "C" void kernel_launch(void* const* d_in, const int* in_sizes, int n_in,
                              void* d_out, int out_size)
{
    const float* query     = (const float*)d_in[0];
    const float* key_value = (const float*)d_in[1];
    const float* Wq = (const float*)d_in[2];
    const float* bq = (const float*)d_in[3];
    const float* Wk = (const float*)d_in[4];
    const float* bk = (const float*)d_in[5];
    const float* Wv = (const float*)d_in[6];
    const float* bv = (const float*)d_in[7];
    const float* Wo = (const float*)d_in[8];
    const float* bo = (const float*)d_in[9];
    const float* g1 = (const float*)d_in[10];
    const float* b1 = (const float*)d_in[11];
    const float* g2 = (const float*)d_in[12];
    const float* b2 = (const float*)d_in[13];
    const float* gate_up = (const float*)d_in[14];
    const float* down    = (const float*)d_in[15];
    float* out = (float*)d_out;

    float *xln, *qb, *kb, *vb, *ctx, *res, *he, *gu, *inter;
    float *wqt, *wkt, *wvt, *wot, *gut, *dnt;
    cudaGetSymbolAddress((void**)&xln,   g_xln);
    cudaGetSymbolAddress((void**)&qb,    g_q);
    cudaGetSymbolAddress((void**)&kb,    g_k);
    cudaGetSymbolAddress((void**)&vb,    g_v);
    cudaGetSymbolAddress((void**)&ctx,   g_ctx);
    cudaGetSymbolAddress((void**)&res,   g_res);
    cudaGetSymbolAddress((void**)&he,    g_he);
    cudaGetSymbolAddress((void**)&gu,    g_gu);
    cudaGetSymbolAddress((void**)&inter, g_int);
    cudaGetSymbolAddress((void**)&wqt,   g_wqt);
    cudaGetSymbolAddress((void**)&wkt,   g_wkt);
    cudaGetSymbolAddress((void**)&wvt,   g_wvt);
    cudaGetSymbolAddress((void**)&wot,   g_wot);
    cudaGetSymbolAddress((void**)&gut,   g_gut);
    cudaGetSymbolAddress((void**)&dnt,   g_dnt);

    cudaFuncSetAttribute(flash_kernel,
        cudaFuncAttributeMaxDynamicSharedMemorySize, FL_SMEM);
    cudaFuncSetAttribute(tc_gemm_kernel,
        cudaFuncAttributeMaxDynamicSharedMemorySize, GM_SMEM);

    // 0. weight transposes ([K,N] -> [N,K])
    transpose_kernel<<<dim3(32, 32), 256>>>(Wq, wqt, HDIM, HDIM);
    transpose_kernel<<<dim3(32, 32), 256>>>(Wk, wkt, HDIM, HDIM);
    transpose_kernel<<<dim3(32, 32), 256>>>(Wv, wvt, HDIM, HDIM);
    transpose_kernel<<<dim3(32, 32), 256>>>(Wo, wot, HDIM, HDIM);
    transpose_kernel<<<dim3(64, 32, NEXP), 256>>>(gate_up, gut, HDIM, 2 * IDIM);
    transpose_kernel<<<dim3(32, 32, NEXP), 256>>>(down, dnt, IDIM, HDIM);

    // 1. LN1
    ln_kernel<<<BATCH * NQ, 256>>>(query, g1, b1, xln, 0);

    // 2-4. Q/K/V projections (tf32 mma.sync tensor cores)
    tc_gemm_kernel<<<dim3(8, 32), 256, GM_SMEM>>>(xln, wqt, bq, nullptr, qb,
                                                  BATCH * NQ, HDIM, 0, 0, 0, 0);
    tc_gemm_kernel<<<dim3(8, 64), 256, GM_SMEM>>>(key_value, wkt, bk, nullptr, kb,
                                                  BATCH * NKV, HDIM, 0, 0, 0, 0);
    tc_gemm_kernel<<<dim3(8, 64), 256, GM_SMEM>>>(key_value, wvt, bv, nullptr, vb,
                                                  BATCH * NKV, HDIM, 0, 0, 0, 0);

    // 5. attention (tensor-core flash)
    flash_kernel<<<dim3(NQ / 128, NH, BATCH), 256, FL_SMEM>>>(qb, kb, vb, ctx);

    // 6. O proj + residual -> res
    tc_gemm_kernel<<<dim3(8, 32), 256, GM_SMEM>>>(ctx, wot, bo, query, res,
                                                  BATCH * NQ, HDIM, 1, 0, 0, 0);

    // 7. LN2 with expert-grouped scatter -> he
    ln_kernel<<<BATCH * NQ, 256>>>(res, g2, b2, he, 1);

    // 8. gate_up GEMM (per expert)
    tc_gemm_kernel<<<dim3(16, 8, NEXP), 256, GM_SMEM>>>(he, gut, nullptr, nullptr, gu,
        BATCH * NQ / NEXP, 2 * IDIM, 0,
        (long)(BATCH * NQ / NEXP) * HDIM,
        (long)2 * IDIM * HDIM,
        (long)(BATCH * NQ / NEXP) * 2 * IDIM);

    // 9. SiLU * up
    silu_kernel<<<(BATCH * NQ * IDIM / 4) / 256, 256>>>(gu, inter);

    // 10. down GEMM, scatter + residual -> out
    tc_gemm_kernel<<<dim3(8, 8, NEXP), 256, GM_SMEM>>>(inter, dnt, nullptr, res, out,
        BATCH * NQ / NEXP, HDIM, 2,
        (long)(BATCH * NQ / NEXP) * IDIM,
        (long)HDIM * IDIM, 0);
}

// round 5
// speedup vs baseline: 6.0236x; 2.2492x over previous
#include <cuda_runtime.h>
#include <cuda_fp16.h>
#include <math.h>
#include <stdint.h>

// Problem constants
#define BATCH 4
#define NQ    1024
#define NKV   2048
#define HDIM  1024
#define NH    16
#define DHEAD 64
#define NEXP  4
#define IDIM  1024

// ---------------------------------------------------------------------------
// Scratch (device globals)
// ---------------------------------------------------------------------------
__device__ __half g_xh   [BATCH*NQ*HDIM];        // LN1 out
__device__ __half g_qh   [BATCH*NQ*HDIM];
__device__ __half g_kh   [BATCH*NKV*HDIM];
__device__ __half g_vh   [BATCH*NKV*HDIM];
__device__ __half g_vt   [BATCH*HDIM*NKV];       // V transposed [b][h*64+d][kv]
__device__ __half g_kvh  [BATCH*NKV*HDIM];       // key_value fp16
__device__ __half g_ctxh [BATCH*NQ*HDIM];
__device__ float  g_res  [BATCH*NQ*HDIM];
__device__ __half g_heh  [BATCH*NQ*HDIM];        // LN2 out, expert-grouped
__device__ __half g_guh  [BATCH*NQ*2*IDIM];
__device__ __half g_inth [BATCH*NQ*IDIM];
// fp16 transposed weights ([N][K], K contiguous)
__device__ __half g_wqt  [HDIM*HDIM];
__device__ __half g_wkt  [HDIM*HDIM];
__device__ __half g_wvt  [HDIM*HDIM];
__device__ __half g_wot  [HDIM*HDIM];
__device__ __half g_gut  [NEXP*2*IDIM*HDIM];
__device__ __half g_dnt  [NEXP*HDIM*IDIM];

// ---------------------------------------------------------------------------
// helpers
// ---------------------------------------------------------------------------
__device__ __forceinline__ uint32_t smem_u32(const void* p) {
    uint32_t a;
    asm("{ .reg .u64 t; cvta.to.shared.u64 t, %1; cvt.u32.u64 %0, t; }"
        : "=r"(a) : "l"(p));
    return a;
}

__device__ __forceinline__ void cp_async16(uint32_t saddr, const void* g) {
    asm volatile("cp.async.cg.shared.global [%0], [%1], 16;\n" :: "r"(saddr), "l"(g));
}

__device__ __forceinline__ float ex2(float x) {
    float r;
    asm("ex2.approx.ftz.f32 %0, %1;" : "=f"(r) : "f"(x));
    return r;
}

// mma.sync m16n8k16 fp16 inputs, fp32 accum
__device__ __forceinline__ void mma_f16(float* c, const uint32_t* a, const uint32_t* b) {
    asm volatile(
        "mma.sync.aligned.m16n8k16.row.col.f32.f16.f16.f32 "
        "{%0,%1,%2,%3}, {%4,%5,%6,%7}, {%8,%9}, {%0,%1,%2,%3};"
        : "+f"(c[0]), "+f"(c[1]), "+f"(c[2]), "+f"(c[3])
        : "r"(a[0]), "r"(a[1]), "r"(a[2]), "r"(a[3]), "r"(b[0]), "r"(b[1]));
}

// ---------------------------------------------------------------------------
// Weight transpose+convert: fp32 in[K][N] -> fp16 out[N][K]
// ---------------------------------------------------------------------------
__global__ __launch_bounds__(256) void transpose_cvt_kernel(
    const float* __restrict__ in, __half* __restrict__ out, int K, int N)
{
    __shared__ float t[32][33];
    in  += (long)blockIdx.z * K * N;
    out += (long)blockIdx.z * K * N;
    int n0 = blockIdx.x * 32, k0 = blockIdx.y * 32;
    int tx = threadIdx.x & 31, ty = threadIdx.x >> 5;
    #pragma unroll
    for (int i = 0; i < 32; i += 8)
        t[ty + i][tx] = in[(long)(k0 + ty + i) * N + n0 + tx];
    __syncthreads();
    #pragma unroll
    for (int i = 0; i < 32; i += 8)
        out[(long)(n0 + ty + i) * K + k0 + tx] = __float2half(t[tx][ty + i]);
}

// fp32 -> fp16 elementwise
__global__ __launch_bounds__(256) void cvt_kernel(
    const float* __restrict__ in, __half* __restrict__ out)
{
    long idx = (long)blockIdx.x * blockDim.x + threadIdx.x;   // float4 idx
    float4 v = *(const float4*)&in[idx * 4];
    uint2 o;
    __half2 h0 = __floats2half2_rn(v.x, v.y);
    __half2 h1 = __floats2half2_rn(v.z, v.w);
    o.x = *(uint32_t*)&h0; o.y = *(uint32_t*)&h1;
    *(uint2*)&out[idx * 4] = o;
}

// V transpose (per batch): vh[b][n][c] -> vt[b][c][n]  (half)
__global__ __launch_bounds__(256) void vtrans_kernel(
    const __half* __restrict__ in, __half* __restrict__ out)
{
    __shared__ __half sh[64][65];
    int b  = blockIdx.z;
    int n0 = blockIdx.x * 64;
    int c0 = blockIdx.y * 64;
    int tid = threadIdx.x;
    #pragma unroll
    for (int i = 0; i < 8; i++) {
        int idx = i * 256 + tid;       // 0..2047 half2
        int row = idx >> 5, cc = idx & 31;
        __half2 v = *(const __half2*)&in[((long)b * NKV + n0 + row) * HDIM + c0 + cc * 2];
        sh[row][cc * 2]     = __low2half(v);
        sh[row][cc * 2 + 1] = __high2half(v);
    }
    __syncthreads();
    #pragma unroll
    for (int i = 0; i < 8; i++) {
        int idx = i * 256 + tid;
        int row = idx >> 5, cc = idx & 31;   // row = c offset, cc*2 = n offset
        __half2 v = __halves2half2(sh[cc * 2][row], sh[cc * 2 + 1][row]);
        *(__half2*)&out[((long)b * HDIM + c0 + row) * NKV + n0 + cc * 2] = v;
    }
}

// ---------------------------------------------------------------------------
// fp16 mma.sync GEMM: C[M,N] = A[M,1024] @ Bt[N,1024]^T (+bias) + epilogue
//   mode 0: C(half) = AB + bias
//   mode 1: C(float) = AB + bias + res
//   mode 2: C(float), MoE scatter: grow = b*1024 + 4*j + e; C[grow*H+n]=res+AB
// Tile 128x128, 8 warps (64x32 each), K-chunk 64 halves, double-buffered.
// smem row stride 72 halves (144B) — conflict-free fragment loads.
// ---------------------------------------------------------------------------
#define GK 1024
#define HST 72
#define HBUF (128 * HST * 2)          // bytes per matrix per stage (18432)
#define HSTAGE (2 * HBUF)             // A+B per stage (36864)
#define GM_SMEM (2 * HSTAGE)          // 73728

__device__ __forceinline__ void gl_load_h(
    const __half* A, const __half* Bt, int m0, int n0, int kc,
    uint32_t sbase, int buf, int tid)
{
    uint32_t abase = sbase + buf * HSTAGE;
    uint32_t bbase = abase + HBUF;
    const __half* ag = A  + (long)m0 * GK + kc * 64;
    const __half* bg = Bt + (long)n0 * GK + kc * 64;
    #pragma unroll
    for (int i = 0; i < 4; i++) {
        int idx = i * 256 + tid;           // 0..1023
        int row = idx >> 3, c = idx & 7;
        uint32_t off = (uint32_t)(row * 144 + c * 16);
        cp_async16(abase + off, ag + (long)row * GK + c * 8);
        cp_async16(bbase + off, bg + (long)row * GK + c * 8);
    }
    asm volatile("cp.async.commit_group;\n" ::: "memory");
}

__global__ __launch_bounds__(256) void tc_gemm_h(
    const __half* __restrict__ A, const __half* __restrict__ Bt,
    const float* __restrict__ bias, const float* __restrict__ res,
    void* __restrict__ Cv, int M, int N, int mode,
    long sA, long sB, long sC)
{
    extern __shared__ __align__(16) __half smem[];
    const int tid = threadIdx.x;
    const int z = blockIdx.z;
    A  += (long)z * sA;
    Bt += (long)z * sB;
    const int m0 = blockIdx.y * 128;
    const int n0 = blockIdx.x * 128;

    const int w    = tid >> 5;
    const int lane = tid & 31;
    const int wm   = w & 1;
    const int wn   = w >> 1;
    const int g    = lane >> 2;
    const int tig  = lane & 3;

    uint32_t sbase = smem_u32(smem);

    float acc[4][4][4];
    #pragma unroll
    for (int mt = 0; mt < 4; mt++)
        #pragma unroll
        for (int nt = 0; nt < 4; nt++)
            acc[mt][nt][0] = acc[mt][nt][1] = acc[mt][nt][2] = acc[mt][nt][3] = 0.f;

    gl_load_h(A, Bt, m0, n0, 0, sbase, 0, tid);

    #pragma unroll 1
    for (int kc = 0; kc < GK / 64; kc++) {
        const int buf = kc & 1;
        asm volatile("cp.async.wait_group 0;\n" ::: "memory");
        __syncthreads();
        if (kc + 1 < GK / 64)
            gl_load_h(A, Bt, m0, n0, kc + 1, sbase, buf ^ 1, tid);

        const char* Asb = (const char*)smem + buf * HSTAGE;
        const char* Bsb = Asb + HBUF;

        #pragma unroll
        for (int ks = 0; ks < 4; ks++) {
            uint32_t af[4][4], bf[4][2];
            #pragma unroll
            for (int mt = 0; mt < 4; mt++) {
                int r = wm * 64 + mt * 16 + g;
                const char* p = Asb + r * 144 + ks * 32 + tig * 4;
                af[mt][0] = *(const uint32_t*)p;
                af[mt][1] = *(const uint32_t*)(p + 8 * 144);
                af[mt][2] = *(const uint32_t*)(p + 16);
                af[mt][3] = *(const uint32_t*)(p + 8 * 144 + 16);
            }
            #pragma unroll
            for (int nt = 0; nt < 4; nt++) {
                int n = wn * 32 + nt * 8 + g;
                const char* p = Bsb + n * 144 + ks * 32 + tig * 4;
                bf[nt][0] = *(const uint32_t*)p;
                bf[nt][1] = *(const uint32_t*)(p + 16);
            }
            #pragma unroll
            for (int mt = 0; mt < 4; mt++)
                #pragma unroll
                for (int nt = 0; nt < 4; nt++)
                    mma_f16(acc[mt][nt], af[mt], bf[nt]);
        }
    }

    // epilogue
    #pragma unroll
    for (int mt = 0; mt < 4; mt++) {
        #pragma unroll
        for (int half = 0; half < 2; half++) {
            int row = m0 + wm * 64 + mt * 16 + g + half * 8;
            long rbase;
            if (mode == 2) {
                int b = row >> 8, jj = row & 255;
                rbase = (((long)b << 10) + (jj << 2) + z) * (long)HDIM;
            } else {
                rbase = (long)row * N + (long)z * sC;
            }
            #pragma unroll
            for (int nt = 0; nt < 4; nt++) {
                int col = n0 + wn * 32 + nt * 8 + tig * 2;
                float vx = acc[mt][nt][half * 2 + 0];
                float vy = acc[mt][nt][half * 2 + 1];
                if (bias) { vx += bias[col]; vy += bias[col + 1]; }
                if (mode == 0) {
                    *(__half2*)((__half*)Cv + rbase + col) = __floats2half2_rn(vx, vy);
                } else {
                    float* C = (float*)Cv;
                    const float2 rr = *(const float2*)&res[rbase + col];
                    float2 o; o.x = vx + rr.x; o.y = vy + rr.y;
                    *(float2*)&C[rbase + col] = o;
                }
            }
        }
    }
}

// ---------------------------------------------------------------------------
// LayerNorm: fp32 in -> fp16 out. scatter=1 -> expert-grouped row order.
// ---------------------------------------------------------------------------
__global__ __launch_bounds__(256) void ln_kernel(
    const float* __restrict__ x, const float* __restrict__ g,
    const float* __restrict__ be, __half* __restrict__ out, int scatter)
{
    const int row = blockIdx.x;
    const int tid = threadIdx.x;
    const float* xr = x + (long)row * HDIM;

    float4 v = *(const float4*)&xr[tid * 4];
    float s  = v.x + v.y + v.z + v.w;
    float s2 = v.x*v.x + v.y*v.y + v.z*v.z + v.w*v.w;

    #pragma unroll
    for (int off = 16; off; off >>= 1) {
        s  += __shfl_xor_sync(0xffffffffu, s,  off);
        s2 += __shfl_xor_sync(0xffffffffu, s2, off);
    }
    __shared__ float rs[8], rs2[8];
    int w = tid >> 5, lane = tid & 31;
    if (lane == 0) { rs[w] = s; rs2[w] = s2; }
    __syncthreads();
    float tot = 0.f, tot2 = 0.f;
    #pragma unroll
    for (int i = 0; i < 8; i++) { tot += rs[i]; tot2 += rs2[i]; }

    float mu   = tot * (1.0f / HDIM);
    float var  = tot2 * (1.0f / HDIM) - mu * mu;
    float rstd = rsqrtf(var + 1e-6f);

    int orow = row;
    if (scatter) {
        int b = row >> 10, q = row & 1023;
        orow = (q & 3) * (BATCH * NQ / NEXP) + b * (NQ / NEXP) + (q >> 2);
    }
    float4 gv = *(const float4*)&g[tid * 4];
    float4 bv = *(const float4*)&be[tid * 4];
    float yx = (v.x - mu) * rstd * gv.x + bv.x;
    float yy = (v.y - mu) * rstd * gv.y + bv.y;
    float yz = (v.z - mu) * rstd * gv.z + bv.z;
    float yw = (v.w - mu) * rstd * gv.w + bv.w;
    __half* o = out + (long)orow * HDIM + tid * 4;
    ((__half2*)o)[0] = __floats2half2_rn(yx, yy);
    ((__half2*)o)[1] = __floats2half2_rn(yz, yw);
}

// ---------------------------------------------------------------------------
// fp16 tensor-core flash attention. Br=128, Bc=64, d=64. 8 warps.
// Warp w owns q-rows [w*16, w*16+16). Scale applied post-MMA in fp32.
// smem (halves): Q[128*72] | K[2][64*72] | Vt[2][64*72] | P[8][16*72]
// ---------------------------------------------------------------------------
#define FQ_OFF      0
#define FK_OFF(b)   (9216 + (b) * 4608)
#define FVT_OFF(b)  (18432 + (b) * 4608)
#define FP_OFF      27648
#define FL_SMEM     ((27648 + 9216) * 2)

__device__ __forceinline__ void fl_load_kv(
    const __half* Kh, const __half* Vt, int b, int h, int n0,
    uint32_t sbase, int buf, int tid)
{
    uint32_t kb = sbase + FK_OFF(buf) * 2;
    uint32_t vb = sbase + FVT_OFF(buf) * 2;
    const __half* kg = Kh + ((long)(b * NKV + n0) << 10) + h * DHEAD;
    const __half* vg = Vt + ((long)b * HDIM + h * DHEAD) * NKV + n0;
    #pragma unroll
    for (int i = 0; i < 2; i++) {
        int idx = i * 256 + tid;          // 0..511
        int row = idx >> 3, c = idx & 7;
        uint32_t off = (uint32_t)(row * 144 + c * 16);
        cp_async16(kb + off, kg + ((long)row << 10) + c * 8);
        cp_async16(vb + off, vg + (long)row * NKV + c * 8);
    }
    asm volatile("cp.async.commit_group;\n" ::: "memory");
}

__global__ __launch_bounds__(256) void flash_h(
    const __half* __restrict__ Qh, const __half* __restrict__ Kh,
    const __half* __restrict__ Vt, __half* __restrict__ O)
{
    extern __shared__ __align__(16) __half fsm[];
    const int tid  = threadIdx.x;
    const int w    = tid >> 5;
    const int lane = tid & 31;
    const int g    = lane >> 2;
    const int tig  = lane & 3;
    const int q0   = blockIdx.x * 128;
    const int h    = blockIdx.y;
    const int b    = blockIdx.z;
    const float SC = 0.125f * 1.44269504088896f;   // scale * log2(e)

    uint32_t sbase = smem_u32(fsm);

    // stage Q tile
    {
        uint32_t qb = sbase + FQ_OFF;
        const __half* qg = Qh + ((long)(b * NQ + q0) << 10) + h * DHEAD;
        #pragma unroll
        for (int i = 0; i < 4; i++) {
            int idx = i * 256 + tid;       // 0..1023
            int row = idx >> 3, c = idx & 7;
            cp_async16(qb + (uint32_t)(row * 144 + c * 16),
                       qg + ((long)row << 10) + c * 8);
        }
        asm volatile("cp.async.commit_group;\n" ::: "memory");
    }
    fl_load_kv(Kh, Vt, b, h, 0, sbase, 0, tid);
    asm volatile("cp.async.wait_group 0;\n" ::: "memory");
    __syncthreads();

    // Q fragments: qf[ks][4], ks over d (4 x k16)
    uint32_t qf[4][4];
    {
        const char* qr = (const char*)fsm + (w * 16 + g) * 144;
        #pragma unroll
        for (int ks = 0; ks < 4; ks++) {
            const char* p = qr + ks * 32 + tig * 4;
            qf[ks][0] = *(const uint32_t*)p;
            qf[ks][1] = *(const uint32_t*)(p + 8 * 144);
            qf[ks][2] = *(const uint32_t*)(p + 16);
            qf[ks][3] = *(const uint32_t*)(p + 8 * 144 + 16);
        }
    }

    float m_lo = -1e30f, m_hi = -1e30f, l_lo = 0.f, l_hi = 0.f;
    float o[8][4];
    #pragma unroll
    for (int nt = 0; nt < 8; nt++)
        o[nt][0] = o[nt][1] = o[nt][2] = o[nt][3] = 0.f;

    __half* Pw = fsm + FP_OFF + w * (16 * HST);

    #pragma unroll 1
    for (int kc = 0; kc < NKV / 64; kc++) {
        const int buf = kc & 1;
        if (kc + 1 < NKV / 64) {
            fl_load_kv(Kh, Vt, b, h, (kc + 1) * 64, sbase, buf ^ 1, tid);
            asm volatile("cp.async.wait_group 1;\n" ::: "memory");
        } else {
            asm volatile("cp.async.wait_group 0;\n" ::: "memory");
        }
        __syncthreads();

        const char* Ks  = (const char*)(fsm + FK_OFF(buf));
        const char* Vts = (const char*)(fsm + FVT_OFF(buf));

        // S = Q @ K^T (raw), then scale by SC in fp32
        float sa[8][4];
        #pragma unroll
        for (int nt = 0; nt < 8; nt++) {
            sa[nt][0] = sa[nt][1] = sa[nt][2] = sa[nt][3] = 0.f;
            #pragma unroll
            for (int ks = 0; ks < 4; ks++) {
                const char* p = Ks + (nt * 8 + g) * 144 + ks * 32 + tig * 4;
                uint32_t bf[2];
                bf[0] = *(const uint32_t*)p;
                bf[1] = *(const uint32_t*)(p + 16);
                mma_f16(sa[nt], qf[ks], bf);
            }
            sa[nt][0] *= SC; sa[nt][1] *= SC; sa[nt][2] *= SC; sa[nt][3] *= SC;
        }

        // online softmax (log2 domain)
        float tmx_lo = sa[0][0], tmx_hi = sa[0][2];
        #pragma unroll
        for (int nt = 0; nt < 8; nt++) {
            tmx_lo = fmaxf(tmx_lo, fmaxf(sa[nt][0], sa[nt][1]));
            tmx_hi = fmaxf(tmx_hi, fmaxf(sa[nt][2], sa[nt][3]));
        }
        tmx_lo = fmaxf(tmx_lo, __shfl_xor_sync(0xffffffffu, tmx_lo, 1));
        tmx_lo = fmaxf(tmx_lo, __shfl_xor_sync(0xffffffffu, tmx_lo, 2));
        tmx_hi = fmaxf(tmx_hi, __shfl_xor_sync(0xffffffffu, tmx_hi, 1));
        tmx_hi = fmaxf(tmx_hi, __shfl_xor_sync(0xffffffffu, tmx_hi, 2));

        float mn_lo = fmaxf(m_lo, tmx_lo);
        float mn_hi = fmaxf(m_hi, tmx_hi);
        float al_lo = ex2(m_lo - mn_lo);
        float al_hi = ex2(m_hi - mn_hi);
        m_lo = mn_lo; m_hi = mn_hi;

        float rs_lo = 0.f, rs_hi = 0.f;
        #pragma unroll
        for (int nt = 0; nt < 8; nt++) {
            float p0 = ex2(sa[nt][0] - mn_lo);
            float p1 = ex2(sa[nt][1] - mn_lo);
            float p2 = ex2(sa[nt][2] - mn_hi);
            float p3 = ex2(sa[nt][3] - mn_hi);
            rs_lo += p0 + p1;
            rs_hi += p2 + p3;
            *(__half2*)&Pw[g * HST + nt * 8 + tig * 2]       = __floats2half2_rn(p0, p1);
            *(__half2*)&Pw[(g + 8) * HST + nt * 8 + tig * 2] = __floats2half2_rn(p2, p3);
        }
        rs_lo += __shfl_xor_sync(0xffffffffu, rs_lo, 1);
        rs_lo += __shfl_xor_sync(0xffffffffu, rs_lo, 2);
        rs_hi += __shfl_xor_sync(0xffffffffu, rs_hi, 1);
        rs_hi += __shfl_xor_sync(0xffffffffu, rs_hi, 2);
        l_lo = l_lo * al_lo + rs_lo;
        l_hi = l_hi * al_hi + rs_hi;
        #pragma unroll
        for (int nt = 0; nt < 8; nt++) {
            o[nt][0] *= al_lo; o[nt][1] *= al_lo;
            o[nt][2] *= al_hi; o[nt][3] *= al_hi;
        }
        __syncwarp();

        // O += P @ V  (A from P strip, B from Vt)
        #pragma unroll
        for (int ks = 0; ks < 4; ks++) {
            const char* pp = (const char*)Pw + g * 144 + ks * 32 + tig * 4;
            uint32_t af[4];
            af[0] = *(const uint32_t*)pp;
            af[1] = *(const uint32_t*)(pp + 8 * 144);
            af[2] = *(const uint32_t*)(pp + 16);
            af[3] = *(const uint32_t*)(pp + 8 * 144 + 16);
            #pragma unroll
            for (int nt = 0; nt < 8; nt++) {
                const char* vp = Vts + (nt * 8 + g) * 144 + ks * 32 + tig * 4;
                uint32_t bf[2];
                bf[0] = *(const uint32_t*)vp;
                bf[1] = *(const uint32_t*)(vp + 16);
                mma_f16(o[nt], af, bf);
            }
        }
        __syncthreads();
    }

    // write ctx (fp16)
    float il_lo = 1.0f / l_lo, il_hi = 1.0f / l_hi;
    int row_lo = q0 + w * 16 + g;
    int row_hi = row_lo + 8;
    #pragma unroll
    for (int nt = 0; nt < 8; nt++) {
        int col = h * DHEAD + nt * 8 + tig * 2;
        *(__half2*)&O[((long)(b * NQ + row_lo) << 10) + col] =
            __floats2half2_rn(o[nt][0] * il_lo, o[nt][1] * il_lo);
        *(__half2*)&O[((long)(b * NQ + row_hi) << 10) + col] =
            __floats2half2_rn(o[nt][2] * il_hi, o[nt][3] * il_hi);
    }
}

// ---------------------------------------------------------------------------
// SiLU(gate) * up : half in/out
// ---------------------------------------------------------------------------
__global__ __launch_bounds__(256) void silu_kernel(
    const __half* __restrict__ gu, __half* __restrict__ inter)
{
    long idx = (long)blockIdx.x * blockDim.x + threadIdx.x;  // half2 idx over inter
    long t  = idx >> 9;              // row (IDIM/2 = 512 half2 per row)
    long c2 = idx & 511;
    __half2 gh = *(const __half2*)&gu[t * (2 * IDIM) + c2 * 2];
    __half2 uh = *(const __half2*)&gu[t * (2 * IDIM) + IDIM + c2 * 2];
    float gx = __low2float(gh), gy = __high2float(gh);
    float ux = __low2float(uh), uy = __high2float(uh);
    float ox = gx / (1.f + __expf(-gx)) * ux;
    float oy = gy / (1.f + __expf(-gy)) * uy;
    *(__half2*)&inter[t * IDIM + c2 * 2] = __floats2half2_rn(ox, oy);
}

// ---------------------------------------------------------------------------
// Launch
// ---------------------------------------------------------------------------
extern "C" void kernel_launch(void* const* d_in, const int* in_sizes, int n_in,
                              void* d_out, int out_size)
{
    const float* query     = (const float*)d_in[0];
    const float* key_value = (const float*)d_in[1];
    const float* Wq = (const float*)d_in[2];
    const float* bq = (const float*)d_in[3];
    const float* Wk = (const float*)d_in[4];
    const float* bk = (const float*)d_in[5];
    const float* Wv = (const float*)d_in[6];
    const float* bv = (const float*)d_in[7];
    const float* Wo = (const float*)d_in[8];
    const float* bo = (const float*)d_in[9];
    const float* g1 = (const float*)d_in[10];
    const float* b1 = (const float*)d_in[11];
    const float* g2 = (const float*)d_in[12];
    const float* b2 = (const float*)d_in[13];
    const float* gate_up = (const float*)d_in[14];
    const float* down    = (const float*)d_in[15];
    float* out = (float*)d_out;

    __half *xh, *qh, *kh, *vh, *vt, *kvh, *ctxh, *heh, *guh, *inth;
    __half *wqt, *wkt, *wvt, *wot, *gut, *dnt;
    float *res;
    cudaGetSymbolAddress((void**)&xh,   g_xh);
    cudaGetSymbolAddress((void**)&qh,   g_qh);
    cudaGetSymbolAddress((void**)&kh,   g_kh);
    cudaGetSymbolAddress((void**)&vh,   g_vh);
    cudaGetSymbolAddress((void**)&vt,   g_vt);
    cudaGetSymbolAddress((void**)&kvh,  g_kvh);
    cudaGetSymbolAddress((void**)&ctxh, g_ctxh);
    cudaGetSymbolAddress((void**)&res,  g_res);
    cudaGetSymbolAddress((void**)&heh,  g_heh);
    cudaGetSymbolAddress((void**)&guh,  g_guh);
    cudaGetSymbolAddress((void**)&inth, g_inth);
    cudaGetSymbolAddress((void**)&wqt,  g_wqt);
    cudaGetSymbolAddress((void**)&wkt,  g_wkt);
    cudaGetSymbolAddress((void**)&wvt,  g_wvt);
    cudaGetSymbolAddress((void**)&wot,  g_wot);
    cudaGetSymbolAddress((void**)&gut,  g_gut);
    cudaGetSymbolAddress((void**)&dnt,  g_dnt);

    cudaFuncSetAttribute(flash_h,
        cudaFuncAttributeMaxDynamicSharedMemorySize, FL_SMEM);
    cudaFuncSetAttribute(tc_gemm_h,
        cudaFuncAttributeMaxDynamicSharedMemorySize, GM_SMEM);

    // 0. weight transpose+cvt, key_value cvt
    transpose_cvt_kernel<<<dim3(32, 32), 256>>>(Wq, wqt, HDIM, HDIM);
    transpose_cvt_kernel<<<dim3(32, 32), 256>>>(Wk, wkt, HDIM, HDIM);
    transpose_cvt_kernel<<<dim3(32, 32), 256>>>(Wv, wvt, HDIM, HDIM);
    transpose_cvt_kernel<<<dim3(32, 32), 256>>>(Wo, wot, HDIM, HDIM);
    transpose_cvt_kernel<<<dim3(64, 32, NEXP), 256>>>(gate_up, gut, HDIM, 2 * IDIM);
    transpose_cvt_kernel<<<dim3(32, 32, NEXP), 256>>>(down, dnt, IDIM, HDIM);
    cvt_kernel<<<(BATCH * NKV * HDIM / 4) / 256, 256>>>(key_value, kvh);

    // 1. LN1 -> fp16
    ln_kernel<<<BATCH * NQ, 256>>>(query, g1, b1, xh, 0);

    // 2-4. Q/K/V projections (fp16 tensor cores)
    tc_gemm_h<<<dim3(8, 32), 256, GM_SMEM>>>(xh,  wqt, bq, nullptr, qh,
                                             BATCH * NQ, HDIM, 0, 0, 0, 0);
    tc_gemm_h<<<dim3(8, 64), 256, GM_SMEM>>>(kvh, wkt, bk, nullptr, kh,
                                             BATCH * NKV, HDIM, 0, 0, 0, 0);
    tc_gemm_h<<<dim3(8, 64), 256, GM_SMEM>>>(kvh, wvt, bv, nullptr, vh,
                                             BATCH * NKV, HDIM, 0, 0, 0, 0);

    // 4b. V transpose -> [b][c][kv]
    vtrans_kernel<<<dim3(NKV / 64, HDIM / 64, BATCH), 256>>>(vh, vt);

    // 5. attention
    flash_h<<<dim3(NQ / 128, NH, BATCH), 256, FL_SMEM>>>(qh, kh, vt, ctxh);

    // 6. O proj + residual -> res (fp32)
    tc_gemm_h<<<dim3(8, 32), 256, GM_SMEM>>>(ctxh, wot, bo, query, res,
                                             BATCH * NQ, HDIM, 1, 0, 0, 0);

    // 7. LN2 (expert-grouped scatter) -> fp16
    ln_kernel<<<BATCH * NQ, 256>>>(res, g2, b2, heh, 1);

    // 8. gate_up GEMM (per expert) -> half
    tc_gemm_h<<<dim3(16, 8, NEXP), 256, GM_SMEM>>>(heh, gut, nullptr, nullptr, guh,
        BATCH * NQ / NEXP, 2 * IDIM, 0,
        (long)(BATCH * NQ / NEXP) * HDIM,
        (long)2 * IDIM * HDIM,
        (long)(BATCH * NQ / NEXP) * 2 * IDIM);

    // 9. SiLU * up -> half
    silu_kernel<<<(BATCH * NQ * IDIM / 2) / 256, 256>>>(guh, inth);

    // 10. down GEMM, scatter + residual -> out (fp32)
    tc_gemm_h<<<dim3(8, 8, NEXP), 256, GM_SMEM>>>(inth, dnt, nullptr, res, out,
        BATCH * NQ / NEXP, HDIM, 2,
        (long)(BATCH * NQ / NEXP) * IDIM,
        (long)HDIM * IDIM, 0);
}

// round 6
// speedup vs baseline: 6.7013x; 1.1125x over previous
#include <cuda_runtime.h>
#include <cuda_fp16.h>
#include <math.h>
#include <stdint.h>

// Problem constants
#define BATCH 4
#define NQ    1024
#define NKV   2048
#define HDIM  1024
#define NH    16
#define DHEAD 64
#define NEXP  4
#define IDIM  1024

// ---------------------------------------------------------------------------
// Scratch (device globals)
// ---------------------------------------------------------------------------
__device__ __half g_xh   [BATCH*NQ*HDIM];
__device__ __half g_qh   [BATCH*NQ*HDIM];
__device__ __half g_kh   [BATCH*NKV*HDIM];
__device__ __half g_vh   [BATCH*NKV*HDIM];
__device__ __half g_vt   [BATCH*HDIM*NKV];
__device__ __half g_kvh  [BATCH*NKV*HDIM];
__device__ __half g_ctxh [BATCH*NQ*HDIM];
__device__ float  g_res  [BATCH*NQ*HDIM];
__device__ __half g_heh  [BATCH*NQ*HDIM];
__device__ __half g_inth [BATCH*NQ*IDIM];
// fp16 transposed weights ([N][K], K contiguous)
__device__ __half g_wqt  [HDIM*HDIM];
__device__ __half g_wkt  [HDIM*HDIM];
__device__ __half g_wvt  [HDIM*HDIM];
__device__ __half g_wot  [HDIM*HDIM];
__device__ __half g_gut  [NEXP*2*IDIM*HDIM];
__device__ __half g_dnt  [NEXP*HDIM*IDIM];

// ---------------------------------------------------------------------------
// helpers
// ---------------------------------------------------------------------------
__device__ __forceinline__ uint32_t smem_u32(const void* p) {
    uint32_t a;
    asm("{ .reg .u64 t; cvta.to.shared.u64 t, %1; cvt.u32.u64 %0, t; }"
        : "=r"(a) : "l"(p));
    return a;
}

__device__ __forceinline__ void cp_async16(uint32_t saddr, const void* g) {
    asm volatile("cp.async.cg.shared.global [%0], [%1], 16;\n" :: "r"(saddr), "l"(g));
}

__device__ __forceinline__ float ex2(float x) {
    float r;
    asm("ex2.approx.ftz.f32 %0, %1;" : "=f"(r) : "f"(x));
    return r;
}

__device__ __forceinline__ void ldsm_x4(uint32_t* r, uint32_t addr) {
    asm volatile("ldmatrix.sync.aligned.m8n8.x4.shared.b16 {%0,%1,%2,%3}, [%4];"
        : "=r"(r[0]), "=r"(r[1]), "=r"(r[2]), "=r"(r[3]) : "r"(addr));
}

// mma.sync m16n8k16 fp16 inputs, fp32 accum
__device__ __forceinline__ void mma_f16(float* c, const uint32_t* a, const uint32_t* b) {
    asm volatile(
        "mma.sync.aligned.m16n8k16.row.col.f32.f16.f16.f32 "
        "{%0,%1,%2,%3}, {%4,%5,%6,%7}, {%8,%9}, {%0,%1,%2,%3};"
        : "+f"(c[0]), "+f"(c[1]), "+f"(c[2]), "+f"(c[3])
        : "r"(a[0]), "r"(a[1]), "r"(a[2]), "r"(a[3]), "r"(b[0]), "r"(b[1]));
}

// per-lane byte offsets for ldmatrix address generation (144B row stride)
// A-type (m16k16 frag): matrices [rows0-7 kLo][rows8-15 kLo][rows0-7 kHi][rows8-15 kHi]
__device__ __forceinline__ uint32_t lds_a_off(int lane) {
    return (uint32_t)(((lane & 7) + (lane & 8)) * 144 + ((lane & 16) ? 16 : 0));
}
// B-type (2 x n8k16 frags): matrices [n0-7 kLo][n0-7 kHi][n8-15 kLo][n8-15 kHi]
__device__ __forceinline__ uint32_t lds_b_off(int lane) {
    return (uint32_t)(((lane & 7) + ((lane & 16) >> 1)) * 144 + ((lane & 8) ? 16 : 0));
}

// ---------------------------------------------------------------------------
// Weight transpose+convert: fp32 in[K][N] -> fp16 out[N][K]
// perm=1: gate_up interleave — out row 2j = col j (gate), 2j+1 = col I+j (up)
// ---------------------------------------------------------------------------
__global__ __launch_bounds__(256) void transpose_cvt_kernel(
    const float* __restrict__ in, __half* __restrict__ out, int K, int N, int perm)
{
    __shared__ float t[32][33];
    in  += (long)blockIdx.z * K * N;
    out += (long)blockIdx.z * K * N;
    int n0 = blockIdx.x * 32, k0 = blockIdx.y * 32;
    int tx = threadIdx.x & 31, ty = threadIdx.x >> 5;
    #pragma unroll
    for (int i = 0; i < 32; i += 8)
        t[ty + i][tx] = in[(long)(k0 + ty + i) * N + n0 + tx];
    __syncthreads();
    #pragma unroll
    for (int i = 0; i < 32; i += 8) {
        int nn = n0 + ty + i;
        int orow = perm ? ((nn < IDIM) ? 2 * nn : 2 * (nn - IDIM) + 1) : nn;
        out[(long)orow * K + k0 + tx] = __float2half(t[tx][ty + i]);
    }
}

// fp32 -> fp16 elementwise
__global__ __launch_bounds__(256) void cvt_kernel(
    const float* __restrict__ in, __half* __restrict__ out)
{
    long idx = (long)blockIdx.x * blockDim.x + threadIdx.x;
    float4 v = *(const float4*)&in[idx * 4];
    uint2 o;
    __half2 h0 = __floats2half2_rn(v.x, v.y);
    __half2 h1 = __floats2half2_rn(v.z, v.w);
    o.x = *(uint32_t*)&h0; o.y = *(uint32_t*)&h1;
    *(uint2*)&out[idx * 4] = o;
}

// V transpose (per batch): vh[b][n][c] -> vt[b][c][n]
__global__ __launch_bounds__(256) void vtrans_kernel(
    const __half* __restrict__ in, __half* __restrict__ out)
{
    __shared__ __half sh[64][65];
    int b  = blockIdx.z;
    int n0 = blockIdx.x * 64;
    int c0 = blockIdx.y * 64;
    int tid = threadIdx.x;
    #pragma unroll
    for (int i = 0; i < 8; i++) {
        int idx = i * 256 + tid;
        int row = idx >> 5, cc = idx & 31;
        __half2 v = *(const __half2*)&in[((long)b * NKV + n0 + row) * HDIM + c0 + cc * 2];
        sh[row][cc * 2]     = __low2half(v);
        sh[row][cc * 2 + 1] = __high2half(v);
    }
    __syncthreads();
    #pragma unroll
    for (int i = 0; i < 8; i++) {
        int idx = i * 256 + tid;
        int row = idx >> 5, cc = idx & 31;
        __half2 v = __halves2half2(sh[cc * 2][row], sh[cc * 2 + 1][row]);
        *(__half2*)&out[((long)b * HDIM + c0 + row) * NKV + n0 + cc * 2] = v;
    }
}

// ---------------------------------------------------------------------------
// fp16 mma.sync GEMM with ldmatrix fragments.
//   mode 0: C(half)  = AB + bias
//   mode 1: C(float) = AB + bias + res
//   mode 2: C(float), MoE scatter + residual
//   mode 3: C(half)  = silu(acc_even) * acc_odd  (fused gate_up; N out = N/2)
// ---------------------------------------------------------------------------
#define GK 1024
#define HST 72
#define HBUF (128 * HST * 2)
#define HSTAGE (2 * HBUF)
#define GM_SMEM (2 * HSTAGE)

__device__ __forceinline__ void gl_load_h(
    const __half* A, const __half* Bt, int m0, int n0, int kc,
    uint32_t sbase, int buf, int tid)
{
    uint32_t abase = sbase + buf * HSTAGE;
    uint32_t bbase = abase + HBUF;
    const __half* ag = A  + (long)m0 * GK + kc * 64;
    const __half* bg = Bt + (long)n0 * GK + kc * 64;
    #pragma unroll
    for (int i = 0; i < 4; i++) {
        int idx = i * 256 + tid;
        int row = idx >> 3, c = idx & 7;
        uint32_t off = (uint32_t)(row * 144 + c * 16);
        cp_async16(abase + off, ag + (long)row * GK + c * 8);
        cp_async16(bbase + off, bg + (long)row * GK + c * 8);
    }
    asm volatile("cp.async.commit_group;\n" ::: "memory");
}

__global__ __launch_bounds__(256) void tc_gemm_h(
    const __half* __restrict__ A, const __half* __restrict__ Bt,
    const float* __restrict__ bias, const float* __restrict__ res,
    void* __restrict__ Cv, int M, int N, int mode,
    long sA, long sB, long sC)
{
    extern __shared__ __align__(16) __half smem[];
    const int tid = threadIdx.x;
    const int z = blockIdx.z;
    A  += (long)z * sA;
    Bt += (long)z * sB;
    const int m0 = blockIdx.y * 128;
    const int n0 = blockIdx.x * 128;

    const int w    = tid >> 5;
    const int lane = tid & 31;
    const int wm   = w & 1;
    const int wn   = w >> 1;
    const int g    = lane >> 2;
    const int tig  = lane & 3;

    uint32_t sbase = smem_u32(smem);
    const uint32_t aoff = lds_a_off(lane);
    const uint32_t boff = lds_b_off(lane);

    float acc[4][4][4];
    #pragma unroll
    for (int mt = 0; mt < 4; mt++)
        #pragma unroll
        for (int nt = 0; nt < 4; nt++)
            acc[mt][nt][0] = acc[mt][nt][1] = acc[mt][nt][2] = acc[mt][nt][3] = 0.f;

    gl_load_h(A, Bt, m0, n0, 0, sbase, 0, tid);

    #pragma unroll 1
    for (int kc = 0; kc < GK / 64; kc++) {
        const int buf = kc & 1;
        asm volatile("cp.async.wait_group 0;\n" ::: "memory");
        __syncthreads();
        if (kc + 1 < GK / 64)
            gl_load_h(A, Bt, m0, n0, kc + 1, sbase, buf ^ 1, tid);

        uint32_t Ab = sbase + buf * HSTAGE;
        uint32_t Bb = Ab + HBUF;

        #pragma unroll
        for (int ks = 0; ks < 4; ks++) {
            uint32_t af[4][4], bf[4][2];
            #pragma unroll
            for (int mt = 0; mt < 4; mt++)
                ldsm_x4(af[mt], Ab + (wm * 64 + mt * 16) * 144 + ks * 32 + aoff);
            #pragma unroll
            for (int nt2 = 0; nt2 < 2; nt2++) {
                uint32_t t4[4];
                ldsm_x4(t4, Bb + (wn * 32 + nt2 * 16) * 144 + ks * 32 + boff);
                bf[nt2 * 2][0] = t4[0]; bf[nt2 * 2][1] = t4[1];
                bf[nt2 * 2 + 1][0] = t4[2]; bf[nt2 * 2 + 1][1] = t4[3];
            }
            #pragma unroll
            for (int mt = 0; mt < 4; mt++)
                #pragma unroll
                for (int nt = 0; nt < 4; nt++)
                    mma_f16(acc[mt][nt], af[mt], bf[nt]);
        }
    }

    // epilogue
    #pragma unroll
    for (int mt = 0; mt < 4; mt++) {
        #pragma unroll
        for (int half = 0; half < 2; half++) {
            int row = m0 + wm * 64 + mt * 16 + g + half * 8;
            long rbase;
            if (mode == 2) {
                int b = row >> 8, jj = row & 255;
                rbase = (((long)b << 10) + (jj << 2) + z) * (long)HDIM;
            } else if (mode == 3) {
                rbase = (long)row * (N >> 1) + (long)z * sC;
            } else {
                rbase = (long)row * N + (long)z * sC;
            }
            #pragma unroll
            for (int nt = 0; nt < 4; nt++) {
                int col = n0 + wn * 32 + nt * 8 + tig * 2;
                float vx = acc[mt][nt][half * 2 + 0];
                float vy = acc[mt][nt][half * 2 + 1];
                if (bias) { vx += bias[col]; vy += bias[col + 1]; }
                if (mode == 0) {
                    *(__half2*)((__half*)Cv + rbase + col) = __floats2half2_rn(vx, vy);
                } else if (mode == 3) {
                    float sx = vx / (1.f + __expf(-vx));
                    ((__half*)Cv)[rbase + (col >> 1)] = __float2half(sx * vy);
                } else {
                    float* C = (float*)Cv;
                    const float2 rr = *(const float2*)&res[rbase + col];
                    float2 o; o.x = vx + rr.x; o.y = vy + rr.y;
                    *(float2*)&C[rbase + col] = o;
                }
            }
        }
    }
}

// ---------------------------------------------------------------------------
// LayerNorm: fp32 in -> fp16 out. scatter=1 -> expert-grouped row order.
// ---------------------------------------------------------------------------
__global__ __launch_bounds__(256) void ln_kernel(
    const float* __restrict__ x, const float* __restrict__ g,
    const float* __restrict__ be, __half* __restrict__ out, int scatter)
{
    const int row = blockIdx.x;
    const int tid = threadIdx.x;
    const float* xr = x + (long)row * HDIM;

    float4 v = *(const float4*)&xr[tid * 4];
    float s  = v.x + v.y + v.z + v.w;
    float s2 = v.x*v.x + v.y*v.y + v.z*v.z + v.w*v.w;

    #pragma unroll
    for (int off = 16; off; off >>= 1) {
        s  += __shfl_xor_sync(0xffffffffu, s,  off);
        s2 += __shfl_xor_sync(0xffffffffu, s2, off);
    }
    __shared__ float rs[8], rs2[8];
    int w = tid >> 5, lane = tid & 31;
    if (lane == 0) { rs[w] = s; rs2[w] = s2; }
    __syncthreads();
    float tot = 0.f, tot2 = 0.f;
    #pragma unroll
    for (int i = 0; i < 8; i++) { tot += rs[i]; tot2 += rs2[i]; }

    float mu   = tot * (1.0f / HDIM);
    float var  = tot2 * (1.0f / HDIM) - mu * mu;
    float rstd = rsqrtf(var + 1e-6f);

    int orow = row;
    if (scatter) {
        int b = row >> 10, q = row & 1023;
        orow = (q & 3) * (BATCH * NQ / NEXP) + b * (NQ / NEXP) + (q >> 2);
    }
    float4 gv = *(const float4*)&g[tid * 4];
    float4 bv = *(const float4*)&be[tid * 4];
    float yx = (v.x - mu) * rstd * gv.x + bv.x;
    float yy = (v.y - mu) * rstd * gv.y + bv.y;
    float yz = (v.z - mu) * rstd * gv.z + bv.z;
    float yw = (v.w - mu) * rstd * gv.w + bv.w;
    __half* o = out + (long)orow * HDIM + tid * 4;
    ((__half2*)o)[0] = __floats2half2_rn(yx, yy);
    ((__half2*)o)[1] = __floats2half2_rn(yz, yw);
}

// ---------------------------------------------------------------------------
// fp16 tensor-core flash attention with ldmatrix. Br=128, Bc=64, d=64.
// ---------------------------------------------------------------------------
#define FQ_OFF      0
#define FK_OFF(b)   (9216 + (b) * 4608)
#define FVT_OFF(b)  (18432 + (b) * 4608)
#define FP_OFF      27648
#define FL_SMEM     ((27648 + 9216) * 2)

__device__ __forceinline__ void fl_load_kv(
    const __half* Kh, const __half* Vt, int b, int h, int n0,
    uint32_t sbase, int buf, int tid)
{
    uint32_t kb = sbase + FK_OFF(buf) * 2;
    uint32_t vb = sbase + FVT_OFF(buf) * 2;
    const __half* kg = Kh + ((long)(b * NKV + n0) << 10) + h * DHEAD;
    const __half* vg = Vt + ((long)b * HDIM + h * DHEAD) * NKV + n0;
    #pragma unroll
    for (int i = 0; i < 2; i++) {
        int idx = i * 256 + tid;
        int row = idx >> 3, c = idx & 7;
        uint32_t off = (uint32_t)(row * 144 + c * 16);
        cp_async16(kb + off, kg + ((long)row << 10) + c * 8);
        cp_async16(vb + off, vg + (long)row * NKV + c * 8);
    }
    asm volatile("cp.async.commit_group;\n" ::: "memory");
}

__global__ __launch_bounds__(256) void flash_h(
    const __half* __restrict__ Qh, const __half* __restrict__ Kh,
    const __half* __restrict__ Vt, __half* __restrict__ O)
{
    extern __shared__ __align__(16) __half fsm[];
    const int tid  = threadIdx.x;
    const int w    = tid >> 5;
    const int lane = tid & 31;
    const int g    = lane >> 2;
    const int tig  = lane & 3;
    const int q0   = blockIdx.x * 128;
    const int h    = blockIdx.y;
    const int b    = blockIdx.z;
    const float SC = 0.125f * 1.44269504088896f;

    uint32_t sbase = smem_u32(fsm);
    const uint32_t aoff = lds_a_off(lane);
    const uint32_t boff = lds_b_off(lane);

    // stage Q tile
    {
        uint32_t qb = sbase + FQ_OFF;
        const __half* qg = Qh + ((long)(b * NQ + q0) << 10) + h * DHEAD;
        #pragma unroll
        for (int i = 0; i < 4; i++) {
            int idx = i * 256 + tid;
            int row = idx >> 3, c = idx & 7;
            cp_async16(qb + (uint32_t)(row * 144 + c * 16),
                       qg + ((long)row << 10) + c * 8);
        }
        asm volatile("cp.async.commit_group;\n" ::: "memory");
    }
    fl_load_kv(Kh, Vt, b, h, 0, sbase, 0, tid);
    asm volatile("cp.async.wait_group 0;\n" ::: "memory");
    __syncthreads();

    // Q fragments via ldmatrix
    uint32_t qf[4][4];
    #pragma unroll
    for (int ks = 0; ks < 4; ks++)
        ldsm_x4(qf[ks], sbase + (w * 16) * 144 + ks * 32 + aoff);

    float m_lo = -1e30f, m_hi = -1e30f, l_lo = 0.f, l_hi = 0.f;
    float o[8][4];
    #pragma unroll
    for (int nt = 0; nt < 8; nt++)
        o[nt][0] = o[nt][1] = o[nt][2] = o[nt][3] = 0.f;

    __half* Pw = fsm + FP_OFF + w * (16 * HST);
    uint32_t Pb = sbase + FP_OFF * 2 + w * (16 * 144);

    #pragma unroll 1
    for (int kc = 0; kc < NKV / 64; kc++) {
        const int buf = kc & 1;
        if (kc + 1 < NKV / 64) {
            fl_load_kv(Kh, Vt, b, h, (kc + 1) * 64, sbase, buf ^ 1, tid);
            asm volatile("cp.async.wait_group 1;\n" ::: "memory");
        } else {
            asm volatile("cp.async.wait_group 0;\n" ::: "memory");
        }
        __syncthreads();

        uint32_t Kb  = sbase + FK_OFF(buf) * 2;
        uint32_t Vtb = sbase + FVT_OFF(buf) * 2;

        // S = Q @ K^T
        float sa[8][4];
        #pragma unroll
        for (int nt = 0; nt < 8; nt++)
            sa[nt][0] = sa[nt][1] = sa[nt][2] = sa[nt][3] = 0.f;
        #pragma unroll
        for (int ks = 0; ks < 4; ks++) {
            uint32_t bf[8][2];
            #pragma unroll
            for (int nt2 = 0; nt2 < 4; nt2++) {
                uint32_t t4[4];
                ldsm_x4(t4, Kb + (nt2 * 16) * 144 + ks * 32 + boff);
                bf[nt2 * 2][0] = t4[0]; bf[nt2 * 2][1] = t4[1];
                bf[nt2 * 2 + 1][0] = t4[2]; bf[nt2 * 2 + 1][1] = t4[3];
            }
            #pragma unroll
            for (int nt = 0; nt < 8; nt++)
                mma_f16(sa[nt], qf[ks], bf[nt]);
        }
        #pragma unroll
        for (int nt = 0; nt < 8; nt++) {
            sa[nt][0] *= SC; sa[nt][1] *= SC; sa[nt][2] *= SC; sa[nt][3] *= SC;
        }

        // online softmax (log2 domain)
        float tmx_lo = sa[0][0], tmx_hi = sa[0][2];
        #pragma unroll
        for (int nt = 0; nt < 8; nt++) {
            tmx_lo = fmaxf(tmx_lo, fmaxf(sa[nt][0], sa[nt][1]));
            tmx_hi = fmaxf(tmx_hi, fmaxf(sa[nt][2], sa[nt][3]));
        }
        tmx_lo = fmaxf(tmx_lo, __shfl_xor_sync(0xffffffffu, tmx_lo, 1));
        tmx_lo = fmaxf(tmx_lo, __shfl_xor_sync(0xffffffffu, tmx_lo, 2));
        tmx_hi = fmaxf(tmx_hi, __shfl_xor_sync(0xffffffffu, tmx_hi, 1));
        tmx_hi = fmaxf(tmx_hi, __shfl_xor_sync(0xffffffffu, tmx_hi, 2));

        float mn_lo = fmaxf(m_lo, tmx_lo);
        float mn_hi = fmaxf(m_hi, tmx_hi);
        float al_lo = ex2(m_lo - mn_lo);
        float al_hi = ex2(m_hi - mn_hi);
        m_lo = mn_lo; m_hi = mn_hi;

        float rs_lo = 0.f, rs_hi = 0.f;
        #pragma unroll
        for (int nt = 0; nt < 8; nt++) {
            float p0 = ex2(sa[nt][0] - mn_lo);
            float p1 = ex2(sa[nt][1] - mn_lo);
            float p2 = ex2(sa[nt][2] - mn_hi);
            float p3 = ex2(sa[nt][3] - mn_hi);
            rs_lo += p0 + p1;
            rs_hi += p2 + p3;
            *(__half2*)&Pw[g * HST + nt * 8 + tig * 2]       = __floats2half2_rn(p0, p1);
            *(__half2*)&Pw[(g + 8) * HST + nt * 8 + tig * 2] = __floats2half2_rn(p2, p3);
        }
        rs_lo += __shfl_xor_sync(0xffffffffu, rs_lo, 1);
        rs_lo += __shfl_xor_sync(0xffffffffu, rs_lo, 2);
        rs_hi += __shfl_xor_sync(0xffffffffu, rs_hi, 1);
        rs_hi += __shfl_xor_sync(0xffffffffu, rs_hi, 2);
        l_lo = l_lo * al_lo + rs_lo;
        l_hi = l_hi * al_hi + rs_hi;
        #pragma unroll
        for (int nt = 0; nt < 8; nt++) {
            o[nt][0] *= al_lo; o[nt][1] *= al_lo;
            o[nt][2] *= al_hi; o[nt][3] *= al_hi;
        }
        __syncwarp();

        // O += P @ V
        #pragma unroll
        for (int ks = 0; ks < 4; ks++) {
            uint32_t af[4];
            ldsm_x4(af, Pb + ks * 32 + aoff);
            uint32_t bf[8][2];
            #pragma unroll
            for (int nt2 = 0; nt2 < 4; nt2++) {
                uint32_t t4[4];
                ldsm_x4(t4, Vtb + (nt2 * 16) * 144 + ks * 32 + boff);
                bf[nt2 * 2][0] = t4[0]; bf[nt2 * 2][1] = t4[1];
                bf[nt2 * 2 + 1][0] = t4[2]; bf[nt2 * 2 + 1][1] = t4[3];
            }
            #pragma unroll
            for (int nt = 0; nt < 8; nt++)
                mma_f16(o[nt], af, bf[nt]);
        }
        __syncthreads();
    }

    float il_lo = 1.0f / l_lo, il_hi = 1.0f / l_hi;
    int row_lo = q0 + w * 16 + g;
    int row_hi = row_lo + 8;
    #pragma unroll
    for (int nt = 0; nt < 8; nt++) {
        int col = h * DHEAD + nt * 8 + tig * 2;
        *(__half2*)&O[((long)(b * NQ + row_lo) << 10) + col] =
            __floats2half2_rn(o[nt][0] * il_lo, o[nt][1] * il_lo);
        *(__half2*)&O[((long)(b * NQ + row_hi) << 10) + col] =
            __floats2half2_rn(o[nt][2] * il_hi, o[nt][3] * il_hi);
    }
}

// ---------------------------------------------------------------------------
// Launch
// ---------------------------------------------------------------------------
extern "C" void kernel_launch(void* const* d_in, const int* in_sizes, int n_in,
                              void* d_out, int out_size)
{
    const float* query     = (const float*)d_in[0];
    const float* key_value = (const float*)d_in[1];
    const float* Wq = (const float*)d_in[2];
    const float* bq = (const float*)d_in[3];
    const float* Wk = (const float*)d_in[4];
    const float* bk = (const float*)d_in[5];
    const float* Wv = (const float*)d_in[6];
    const float* bv = (const float*)d_in[7];
    const float* Wo = (const float*)d_in[8];
    const float* bo = (const float*)d_in[9];
    const float* g1 = (const float*)d_in[10];
    const float* b1 = (const float*)d_in[11];
    const float* g2 = (const float*)d_in[12];
    const float* b2 = (const float*)d_in[13];
    const float* gate_up = (const float*)d_in[14];
    const float* down    = (const float*)d_in[15];
    float* out = (float*)d_out;

    __half *xh, *qh, *kh, *vh, *vt, *kvh, *ctxh, *heh, *inth;
    __half *wqt, *wkt, *wvt, *wot, *gut, *dnt;
    float *res;
    cudaGetSymbolAddress((void**)&xh,   g_xh);
    cudaGetSymbolAddress((void**)&qh,   g_qh);
    cudaGetSymbolAddress((void**)&kh,   g_kh);
    cudaGetSymbolAddress((void**)&vh,   g_vh);
    cudaGetSymbolAddress((void**)&vt,   g_vt);
    cudaGetSymbolAddress((void**)&kvh,  g_kvh);
    cudaGetSymbolAddress((void**)&ctxh, g_ctxh);
    cudaGetSymbolAddress((void**)&res,  g_res);
    cudaGetSymbolAddress((void**)&heh,  g_heh);
    cudaGetSymbolAddress((void**)&inth, g_inth);
    cudaGetSymbolAddress((void**)&wqt,  g_wqt);
    cudaGetSymbolAddress((void**)&wkt,  g_wkt);
    cudaGetSymbolAddress((void**)&wvt,  g_wvt);
    cudaGetSymbolAddress((void**)&wot,  g_wot);
    cudaGetSymbolAddress((void**)&gut,  g_gut);
    cudaGetSymbolAddress((void**)&dnt,  g_dnt);

    cudaFuncSetAttribute(flash_h,
        cudaFuncAttributeMaxDynamicSharedMemorySize, FL_SMEM);
    cudaFuncSetAttribute(tc_gemm_h,
        cudaFuncAttributeMaxDynamicSharedMemorySize, GM_SMEM);

    // 0. weight transpose+cvt, key_value cvt
    transpose_cvt_kernel<<<dim3(32, 32), 256>>>(Wq, wqt, HDIM, HDIM, 0);
    transpose_cvt_kernel<<<dim3(32, 32), 256>>>(Wk, wkt, HDIM, HDIM, 0);
    transpose_cvt_kernel<<<dim3(32, 32), 256>>>(Wv, wvt, HDIM, HDIM, 0);
    transpose_cvt_kernel<<<dim3(32, 32), 256>>>(Wo, wot, HDIM, HDIM, 0);
    transpose_cvt_kernel<<<dim3(64, 32, NEXP), 256>>>(gate_up, gut, HDIM, 2 * IDIM, 1);
    transpose_cvt_kernel<<<dim3(32, 32, NEXP), 256>>>(down, dnt, IDIM, HDIM, 0);
    cvt_kernel<<<(BATCH * NKV * HDIM / 4) / 256, 256>>>(key_value, kvh);

    // 1. LN1 -> fp16
    ln_kernel<<<BATCH * NQ, 256>>>(query, g1, b1, xh, 0);

    // 2-4. Q/K/V projections
    tc_gemm_h<<<dim3(8, 32), 256, GM_SMEM>>>(xh,  wqt, bq, nullptr, qh,
                                             BATCH * NQ, HDIM, 0, 0, 0, 0);
    tc_gemm_h<<<dim3(8, 64), 256, GM_SMEM>>>(kvh, wkt, bk, nullptr, kh,
                                             BATCH * NKV, HDIM, 0, 0, 0, 0);
    tc_gemm_h<<<dim3(8, 64), 256, GM_SMEM>>>(kvh, wvt, bv, nullptr, vh,
                                             BATCH * NKV, HDIM, 0, 0, 0, 0);

    // 4b. V transpose
    vtrans_kernel<<<dim3(NKV / 64, HDIM / 64, BATCH), 256>>>(vh, vt);

    // 5. attention
    flash_h<<<dim3(NQ / 128, NH, BATCH), 256, FL_SMEM>>>(qh, kh, vt, ctxh);

    // 6. O proj + residual -> res (fp32)
    tc_gemm_h<<<dim3(8, 32), 256, GM_SMEM>>>(ctxh, wot, bo, query, res,
                                             BATCH * NQ, HDIM, 1, 0, 0, 0);

    // 7. LN2 (expert-grouped scatter) -> fp16
    ln_kernel<<<BATCH * NQ, 256>>>(res, g2, b2, heh, 1);

    // 8. gate_up GEMM + fused SiLU (per expert) -> inth (half)
    tc_gemm_h<<<dim3(16, 8, NEXP), 256, GM_SMEM>>>(heh, gut, nullptr, nullptr, inth,
        BATCH * NQ / NEXP, 2 * IDIM, 3,
        (long)(BATCH * NQ / NEXP) * HDIM,
        (long)2 * IDIM * HDIM,
        (long)(BATCH * NQ / NEXP) * IDIM);

    // 9. down GEMM, scatter + residual -> out (fp32)
    tc_gemm_h<<<dim3(8, 8, NEXP), 256, GM_SMEM>>>(inth, dnt, nullptr, res, out,
        BATCH * NQ / NEXP, HDIM, 2,
        (long)(BATCH * NQ / NEXP) * IDIM,
        (long)HDIM * IDIM, 0);
}

// round 7
// speedup vs baseline: 6.7114x; 1.0015x over previous
#include <cuda_runtime.h>
#include <cuda_fp16.h>
#include <math.h>
#include <stdint.h>

// Problem constants
#define BATCH 4
#define NQ    1024
#define NKV   2048
#define HDIM  1024
#define NH    16
#define DHEAD 64
#define NEXP  4
#define IDIM  1024

// ---------------------------------------------------------------------------
// Scratch (device globals)
// ---------------------------------------------------------------------------
__device__ __half g_xh   [BATCH*NQ*HDIM];
__device__ __half g_qh   [BATCH*NQ*HDIM];
__device__ __half g_kh   [BATCH*NKV*HDIM];
__device__ __half g_vt   [BATCH*HDIM*NKV];       // V transposed [b][c][kv]
__device__ __half g_kvh  [BATCH*NKV*HDIM];
__device__ __half g_ctxh [BATCH*NQ*HDIM];
__device__ float  g_res  [BATCH*NQ*HDIM];
__device__ __half g_heh  [BATCH*NQ*HDIM];
__device__ __half g_inth [BATCH*NQ*IDIM];
// fp16 transposed weights ([N][K], K contiguous)
__device__ __half g_wqt  [HDIM*HDIM];
__device__ __half g_wkt  [HDIM*HDIM];
__device__ __half g_wvt  [HDIM*HDIM];
__device__ __half g_wot  [HDIM*HDIM];
__device__ __half g_gut  [NEXP*2*IDIM*HDIM];
__device__ __half g_dnt  [NEXP*HDIM*IDIM];

// ---------------------------------------------------------------------------
// helpers
// ---------------------------------------------------------------------------
__device__ __forceinline__ uint32_t smem_u32(const void* p) {
    uint32_t a;
    asm("{ .reg .u64 t; cvta.to.shared.u64 t, %1; cvt.u32.u64 %0, t; }"
        : "=r"(a) : "l"(p));
    return a;
}

__device__ __forceinline__ void cp_async16(uint32_t saddr, const void* g) {
    asm volatile("cp.async.cg.shared.global [%0], [%1], 16;\n" :: "r"(saddr), "l"(g));
}

__device__ __forceinline__ float ex2(float x) {
    float r;
    asm("ex2.approx.ftz.f32 %0, %1;" : "=f"(r) : "f"(x));
    return r;
}

__device__ __forceinline__ void ldsm_x4(uint32_t* r, uint32_t addr) {
    asm volatile("ldmatrix.sync.aligned.m8n8.x4.shared.b16 {%0,%1,%2,%3}, [%4];"
        : "=r"(r[0]), "=r"(r[1]), "=r"(r[2]), "=r"(r[3]) : "r"(addr));
}

__device__ __forceinline__ void mma_f16(float* c, const uint32_t* a, const uint32_t* b) {
    asm volatile(
        "mma.sync.aligned.m16n8k16.row.col.f32.f16.f16.f32 "
        "{%0,%1,%2,%3}, {%4,%5,%6,%7}, {%8,%9}, {%0,%1,%2,%3};"
        : "+f"(c[0]), "+f"(c[1]), "+f"(c[2]), "+f"(c[3])
        : "r"(a[0]), "r"(a[1]), "r"(a[2]), "r"(a[3]), "r"(b[0]), "r"(b[1]));
}

// per-lane byte offsets for ldmatrix (144B row stride)
__device__ __forceinline__ uint32_t lds_a_off(int lane) {
    return (uint32_t)(((lane & 7) + (lane & 8)) * 144 + ((lane & 16) ? 16 : 0));
}
__device__ __forceinline__ uint32_t lds_b_off(int lane) {
    return (uint32_t)(((lane & 7) + ((lane & 16) >> 1)) * 144 + ((lane & 8) ? 16 : 0));
}

// ---------------------------------------------------------------------------
// Weight transpose+convert kernels
// ---------------------------------------------------------------------------
struct TP4 { const float* in[4]; __half* out[4]; };

__global__ __launch_bounds__(256) void transpose4_kernel(TP4 p, int K, int N)
{
    __shared__ float t[32][33];
    const float* in = p.in[blockIdx.z];
    __half* out     = p.out[blockIdx.z];
    int n0 = blockIdx.x * 32, k0 = blockIdx.y * 32;
    int tx = threadIdx.x & 31, ty = threadIdx.x >> 5;
    #pragma unroll
    for (int i = 0; i < 32; i += 8)
        t[ty + i][tx] = in[(long)(k0 + ty + i) * N + n0 + tx];
    __syncthreads();
    #pragma unroll
    for (int i = 0; i < 32; i += 8)
        out[(long)(n0 + ty + i) * K + k0 + tx] = __float2half(t[tx][ty + i]);
}

// per-expert transpose (z = expert), perm=1 interleaves gate/up rows
__global__ __launch_bounds__(256) void transpose_cvt_kernel(
    const float* __restrict__ in, __half* __restrict__ out, int K, int N, int perm)
{
    __shared__ float t[32][33];
    in  += (long)blockIdx.z * K * N;
    out += (long)blockIdx.z * K * N;
    int n0 = blockIdx.x * 32, k0 = blockIdx.y * 32;
    int tx = threadIdx.x & 31, ty = threadIdx.x >> 5;
    #pragma unroll
    for (int i = 0; i < 32; i += 8)
        t[ty + i][tx] = in[(long)(k0 + ty + i) * N + n0 + tx];
    __syncthreads();
    #pragma unroll
    for (int i = 0; i < 32; i += 8) {
        int nn = n0 + ty + i;
        int orow = perm ? ((nn < IDIM) ? 2 * nn : 2 * (nn - IDIM) + 1) : nn;
        out[(long)orow * K + k0 + tx] = __float2half(t[tx][ty + i]);
    }
}

// fp32 -> fp16 elementwise
__global__ __launch_bounds__(256) void cvt_kernel(
    const float* __restrict__ in, __half* __restrict__ out)
{
    long idx = (long)blockIdx.x * blockDim.x + threadIdx.x;
    float4 v = *(const float4*)&in[idx * 4];
    uint2 o;
    __half2 h0 = __floats2half2_rn(v.x, v.y);
    __half2 h1 = __floats2half2_rn(v.z, v.w);
    o.x = *(uint32_t*)&h0; o.y = *(uint32_t*)&h1;
    *(uint2*)&out[idx * 4] = o;
}

// ---------------------------------------------------------------------------
// fp16 mma.sync GEMM with ldmatrix fragments.
//   mode 0: C(half)  = AB + bias
//   mode 1: C(float) = AB + bias + res
//   mode 2: C(float), MoE scatter + residual
//   mode 3: C(half)  = silu(acc_even) * acc_odd  (fused gate_up; N out = N/2)
//   mode 4: C(half)  = (AB + bias)^T scattered to vt[b][c][kv] (V projection)
// ---------------------------------------------------------------------------
#define GK 1024
#define HST 72
#define HBUF (128 * HST * 2)
#define HSTAGE (2 * HBUF)
#define GM_SMEM (2 * HSTAGE)

__device__ __forceinline__ void gl_load_h(
    const __half* A, const __half* Bt, int m0, int n0, int kc,
    uint32_t sbase, int buf, int tid)
{
    uint32_t abase = sbase + buf * HSTAGE;
    uint32_t bbase = abase + HBUF;
    const __half* ag = A  + (long)m0 * GK + kc * 64;
    const __half* bg = Bt + (long)n0 * GK + kc * 64;
    #pragma unroll
    for (int i = 0; i < 4; i++) {
        int idx = i * 256 + tid;
        int row = idx >> 3, c = idx & 7;
        uint32_t off = (uint32_t)(row * 144 + c * 16);
        cp_async16(abase + off, ag + (long)row * GK + c * 8);
        cp_async16(bbase + off, bg + (long)row * GK + c * 8);
    }
    asm volatile("cp.async.commit_group;\n" ::: "memory");
}

__global__ __launch_bounds__(256, 2) void tc_gemm_h(
    const __half* __restrict__ A, const __half* __restrict__ Bt,
    const float* __restrict__ bias, const float* __restrict__ res,
    void* __restrict__ Cv, int M, int N, int mode,
    long sA, long sB, long sC)
{
    extern __shared__ __align__(16) __half smem[];
    const int tid = threadIdx.x;
    const int z = blockIdx.z;
    A  += (long)z * sA;
    Bt += (long)z * sB;
    const int m0 = blockIdx.y * 128;
    const int n0 = blockIdx.x * 128;

    const int w    = tid >> 5;
    const int lane = tid & 31;
    const int wm   = w & 1;
    const int wn   = w >> 1;
    const int g    = lane >> 2;
    const int tig  = lane & 3;

    uint32_t sbase = smem_u32(smem);
    const uint32_t aoff = lds_a_off(lane);
    const uint32_t boff = lds_b_off(lane);

    float acc[4][4][4];
    #pragma unroll
    for (int mt = 0; mt < 4; mt++)
        #pragma unroll
        for (int nt = 0; nt < 4; nt++)
            acc[mt][nt][0] = acc[mt][nt][1] = acc[mt][nt][2] = acc[mt][nt][3] = 0.f;

    gl_load_h(A, Bt, m0, n0, 0, sbase, 0, tid);

    #pragma unroll 1
    for (int kc = 0; kc < GK / 64; kc++) {
        const int buf = kc & 1;
        asm volatile("cp.async.wait_group 0;\n" ::: "memory");
        __syncthreads();
        if (kc + 1 < GK / 64)
            gl_load_h(A, Bt, m0, n0, kc + 1, sbase, buf ^ 1, tid);

        uint32_t Ab = sbase + buf * HSTAGE;
        uint32_t Bb = Ab + HBUF;

        #pragma unroll
        for (int ks = 0; ks < 4; ks++) {
            uint32_t af[4][4], bf[4][2];
            #pragma unroll
            for (int mt = 0; mt < 4; mt++)
                ldsm_x4(af[mt], Ab + (wm * 64 + mt * 16) * 144 + ks * 32 + aoff);
            #pragma unroll
            for (int nt2 = 0; nt2 < 2; nt2++) {
                uint32_t t4[4];
                ldsm_x4(t4, Bb + (wn * 32 + nt2 * 16) * 144 + ks * 32 + boff);
                bf[nt2 * 2][0] = t4[0]; bf[nt2 * 2][1] = t4[1];
                bf[nt2 * 2 + 1][0] = t4[2]; bf[nt2 * 2 + 1][1] = t4[3];
            }
            #pragma unroll
            for (int mt = 0; mt < 4; mt++)
                #pragma unroll
                for (int nt = 0; nt < 4; nt++)
                    mma_f16(acc[mt][nt], af[mt], bf[nt]);
        }
    }

    if (mode == 4) {
        // transposed epilogue: stage tile [token][chan] then write vt[b][chan][token]
        __syncthreads();
        __half* st = smem;                       // [128][130] halves
        #pragma unroll
        for (int mt = 0; mt < 4; mt++) {
            #pragma unroll
            for (int hf = 0; hf < 2; hf++) {
                int lr = wm * 64 + mt * 16 + g + hf * 8;
                #pragma unroll
                for (int nt = 0; nt < 4; nt++) {
                    int lc = wn * 32 + nt * 8 + tig * 2;
                    float vx = acc[mt][nt][hf * 2 + 0] + bias[n0 + lc];
                    float vy = acc[mt][nt][hf * 2 + 1] + bias[n0 + lc + 1];
                    *(__half2*)&st[lr * 130 + lc] = __floats2half2_rn(vx, vy);
                }
            }
        }
        __syncthreads();
        int b     = m0 >> 11;            // NKV = 2048 tokens per batch
        int ntok0 = m0 & (NKV - 1);
        __half* vt = (__half*)Cv;
        #pragma unroll
        for (int i = tid; i < 128 * 64; i += 256) {
            int c = i >> 6, n2 = i & 63;
            __half2 v = __halves2half2(st[(n2 * 2) * 130 + c],
                                       st[(n2 * 2 + 1) * 130 + c]);
            *(__half2*)&vt[((long)b * HDIM + n0 + c) * NKV + ntok0 + n2 * 2] = v;
        }
        return;
    }

    // epilogue (modes 0-3)
    #pragma unroll
    for (int mt = 0; mt < 4; mt++) {
        #pragma unroll
        for (int half = 0; half < 2; half++) {
            int row = m0 + wm * 64 + mt * 16 + g + half * 8;
            long rbase;
            if (mode == 2) {
                int b = row >> 8, jj = row & 255;
                rbase = (((long)b << 10) + (jj << 2) + z) * (long)HDIM;
            } else if (mode == 3) {
                rbase = (long)row * (N >> 1) + (long)z * sC;
            } else {
                rbase = (long)row * N + (long)z * sC;
            }
            #pragma unroll
            for (int nt = 0; nt < 4; nt++) {
                int col = n0 + wn * 32 + nt * 8 + tig * 2;
                float vx = acc[mt][nt][half * 2 + 0];
                float vy = acc[mt][nt][half * 2 + 1];
                if (bias) { vx += bias[col]; vy += bias[col + 1]; }
                if (mode == 0) {
                    *(__half2*)((__half*)Cv + rbase + col) = __floats2half2_rn(vx, vy);
                } else if (mode == 3) {
                    float sx = vx / (1.f + __expf(-vx));
                    ((__half*)Cv)[rbase + (col >> 1)] = __float2half(sx * vy);
                } else {
                    float* C = (float*)Cv;
                    const float2 rr = *(const float2*)&res[rbase + col];
                    float2 o; o.x = vx + rr.x; o.y = vy + rr.y;
                    *(float2*)&C[rbase + col] = o;
                }
            }
        }
    }
}

// ---------------------------------------------------------------------------
// LayerNorm: fp32 in -> fp16 out. scatter=1 -> expert-grouped row order.
// ---------------------------------------------------------------------------
__global__ __launch_bounds__(256) void ln_kernel(
    const float* __restrict__ x, const float* __restrict__ g,
    const float* __restrict__ be, __half* __restrict__ out, int scatter)
{
    const int row = blockIdx.x;
    const int tid = threadIdx.x;
    const float* xr = x + (long)row * HDIM;

    float4 v = *(const float4*)&xr[tid * 4];
    float s  = v.x + v.y + v.z + v.w;
    float s2 = v.x*v.x + v.y*v.y + v.z*v.z + v.w*v.w;

    #pragma unroll
    for (int off = 16; off; off >>= 1) {
        s  += __shfl_xor_sync(0xffffffffu, s,  off);
        s2 += __shfl_xor_sync(0xffffffffu, s2, off);
    }
    __shared__ float rs[8], rs2[8];
    int w = tid >> 5, lane = tid & 31;
    if (lane == 0) { rs[w] = s; rs2[w] = s2; }
    __syncthreads();
    float tot = 0.f, tot2 = 0.f;
    #pragma unroll
    for (int i = 0; i < 8; i++) { tot += rs[i]; tot2 += rs2[i]; }

    float mu   = tot * (1.0f / HDIM);
    float var  = tot2 * (1.0f / HDIM) - mu * mu;
    float rstd = rsqrtf(var + 1e-6f);

    int orow = row;
    if (scatter) {
        int b = row >> 10, q = row & 1023;
        orow = (q & 3) * (BATCH * NQ / NEXP) + b * (NQ / NEXP) + (q >> 2);
    }
    float4 gv = *(const float4*)&g[tid * 4];
    float4 bv = *(const float4*)&be[tid * 4];
    float yx = (v.x - mu) * rstd * gv.x + bv.x;
    float yy = (v.y - mu) * rstd * gv.y + bv.y;
    float yz = (v.z - mu) * rstd * gv.z + bv.z;
    float yw = (v.w - mu) * rstd * gv.w + bv.w;
    __half* o = out + (long)orow * HDIM + tid * 4;
    ((__half2*)o)[0] = __floats2half2_rn(yx, yy);
    ((__half2*)o)[1] = __floats2half2_rn(yz, yw);
}

// ---------------------------------------------------------------------------
// fp16 tensor-core flash attention with ldmatrix. Br=128, Bc=64, d=64.
// ---------------------------------------------------------------------------
#define FQ_OFF      0
#define FK_OFF(b)   (9216 + (b) * 4608)
#define FVT_OFF(b)  (18432 + (b) * 4608)
#define FP_OFF      27648
#define FL_SMEM     ((27648 + 9216) * 2)

__device__ __forceinline__ void fl_load_kv(
    const __half* Kh, const __half* Vt, int b, int h, int n0,
    uint32_t sbase, int buf, int tid)
{
    uint32_t kb = sbase + FK_OFF(buf) * 2;
    uint32_t vb = sbase + FVT_OFF(buf) * 2;
    const __half* kg = Kh + ((long)(b * NKV + n0) << 10) + h * DHEAD;
    const __half* vg = Vt + ((long)b * HDIM + h * DHEAD) * NKV + n0;
    #pragma unroll
    for (int i = 0; i < 2; i++) {
        int idx = i * 256 + tid;
        int row = idx >> 3, c = idx & 7;
        uint32_t off = (uint32_t)(row * 144 + c * 16);
        cp_async16(kb + off, kg + ((long)row << 10) + c * 8);
        cp_async16(vb + off, vg + (long)row * NKV + c * 8);
    }
    asm volatile("cp.async.commit_group;\n" ::: "memory");
}

__global__ __launch_bounds__(256, 2) void flash_h(
    const __half* __restrict__ Qh, const __half* __restrict__ Kh,
    const __half* __restrict__ Vt, __half* __restrict__ O)
{
    extern __shared__ __align__(16) __half fsm[];
    const int tid  = threadIdx.x;
    const int w    = tid >> 5;
    const int lane = tid & 31;
    const int g    = lane >> 2;
    const int tig  = lane & 3;
    const int q0   = blockIdx.x * 128;
    const int h    = blockIdx.y;
    const int b    = blockIdx.z;
    const float SC = 0.125f * 1.44269504088896f;

    uint32_t sbase = smem_u32(fsm);
    const uint32_t aoff = lds_a_off(lane);
    const uint32_t boff = lds_b_off(lane);

    // stage Q tile
    {
        uint32_t qb = sbase + FQ_OFF;
        const __half* qg = Qh + ((long)(b * NQ + q0) << 10) + h * DHEAD;
        #pragma unroll
        for (int i = 0; i < 4; i++) {
            int idx = i * 256 + tid;
            int row = idx >> 3, c = idx & 7;
            cp_async16(qb + (uint32_t)(row * 144 + c * 16),
                       qg + ((long)row << 10) + c * 8);
        }
        asm volatile("cp.async.commit_group;\n" ::: "memory");
    }
    fl_load_kv(Kh, Vt, b, h, 0, sbase, 0, tid);
    asm volatile("cp.async.wait_group 0;\n" ::: "memory");
    __syncthreads();

    uint32_t qf[4][4];
    #pragma unroll
    for (int ks = 0; ks < 4; ks++)
        ldsm_x4(qf[ks], sbase + (w * 16) * 144 + ks * 32 + aoff);

    float m_lo = -1e30f, m_hi = -1e30f, l_lo = 0.f, l_hi = 0.f;
    float o[8][4];
    #pragma unroll
    for (int nt = 0; nt < 8; nt++)
        o[nt][0] = o[nt][1] = o[nt][2] = o[nt][3] = 0.f;

    __half* Pw = fsm + FP_OFF + w * (16 * HST);
    uint32_t Pb = sbase + FP_OFF * 2 + w * (16 * 144);

    #pragma unroll 1
    for (int kc = 0; kc < NKV / 64; kc++) {
        const int buf = kc & 1;
        if (kc + 1 < NKV / 64) {
            fl_load_kv(Kh, Vt, b, h, (kc + 1) * 64, sbase, buf ^ 1, tid);
            asm volatile("cp.async.wait_group 1;\n" ::: "memory");
        } else {
            asm volatile("cp.async.wait_group 0;\n" ::: "memory");
        }
        __syncthreads();

        uint32_t Kb  = sbase + FK_OFF(buf) * 2;
        uint32_t Vtb = sbase + FVT_OFF(buf) * 2;

        float sa[8][4];
        #pragma unroll
        for (int nt = 0; nt < 8; nt++)
            sa[nt][0] = sa[nt][1] = sa[nt][2] = sa[nt][3] = 0.f;
        #pragma unroll
        for (int ks = 0; ks < 4; ks++) {
            uint32_t bf[8][2];
            #pragma unroll
            for (int nt2 = 0; nt2 < 4; nt2++) {
                uint32_t t4[4];
                ldsm_x4(t4, Kb + (nt2 * 16) * 144 + ks * 32 + boff);
                bf[nt2 * 2][0] = t4[0]; bf[nt2 * 2][1] = t4[1];
                bf[nt2 * 2 + 1][0] = t4[2]; bf[nt2 * 2 + 1][1] = t4[3];
            }
            #pragma unroll
            for (int nt = 0; nt < 8; nt++)
                mma_f16(sa[nt], qf[ks], bf[nt]);
        }
        #pragma unroll
        for (int nt = 0; nt < 8; nt++) {
            sa[nt][0] *= SC; sa[nt][1] *= SC; sa[nt][2] *= SC; sa[nt][3] *= SC;
        }

        float tmx_lo = sa[0][0], tmx_hi = sa[0][2];
        #pragma unroll
        for (int nt = 0; nt < 8; nt++) {
            tmx_lo = fmaxf(tmx_lo, fmaxf(sa[nt][0], sa[nt][1]));
            tmx_hi = fmaxf(tmx_hi, fmaxf(sa[nt][2], sa[nt][3]));
        }
        tmx_lo = fmaxf(tmx_lo, __shfl_xor_sync(0xffffffffu, tmx_lo, 1));
        tmx_lo = fmaxf(tmx_lo, __shfl_xor_sync(0xffffffffu, tmx_lo, 2));
        tmx_hi = fmaxf(tmx_hi, __shfl_xor_sync(0xffffffffu, tmx_hi, 1));
        tmx_hi = fmaxf(tmx_hi, __shfl_xor_sync(0xffffffffu, tmx_hi, 2));

        float mn_lo = fmaxf(m_lo, tmx_lo);
        float mn_hi = fmaxf(m_hi, tmx_hi);
        float al_lo = ex2(m_lo - mn_lo);
        float al_hi = ex2(m_hi - mn_hi);
        m_lo = mn_lo; m_hi = mn_hi;

        float rs_lo = 0.f, rs_hi = 0.f;
        #pragma unroll
        for (int nt = 0; nt < 8; nt++) {
            float p0 = ex2(sa[nt][0] - mn_lo);
            float p1 = ex2(sa[nt][1] - mn_lo);
            float p2 = ex2(sa[nt][2] - mn_hi);
            float p3 = ex2(sa[nt][3] - mn_hi);
            rs_lo += p0 + p1;
            rs_hi += p2 + p3;
            *(__half2*)&Pw[g * HST + nt * 8 + tig * 2]       = __floats2half2_rn(p0, p1);
            *(__half2*)&Pw[(g + 8) * HST + nt * 8 + tig * 2] = __floats2half2_rn(p2, p3);
        }
        rs_lo += __shfl_xor_sync(0xffffffffu, rs_lo, 1);
        rs_lo += __shfl_xor_sync(0xffffffffu, rs_lo, 2);
        rs_hi += __shfl_xor_sync(0xffffffffu, rs_hi, 1);
        rs_hi += __shfl_xor_sync(0xffffffffu, rs_hi, 2);
        l_lo = l_lo * al_lo + rs_lo;
        l_hi = l_hi * al_hi + rs_hi;
        #pragma unroll
        for (int nt = 0; nt < 8; nt++) {
            o[nt][0] *= al_lo; o[nt][1] *= al_lo;
            o[nt][2] *= al_hi; o[nt][3] *= al_hi;
        }
        __syncwarp();

        #pragma unroll
        for (int ks = 0; ks < 4; ks++) {
            uint32_t af[4];
            ldsm_x4(af, Pb + ks * 32 + aoff);
            uint32_t bf[8][2];
            #pragma unroll
            for (int nt2 = 0; nt2 < 4; nt2++) {
                uint32_t t4[4];
                ldsm_x4(t4, Vtb + (nt2 * 16) * 144 + ks * 32 + boff);
                bf[nt2 * 2][0] = t4[0]; bf[nt2 * 2][1] = t4[1];
                bf[nt2 * 2 + 1][0] = t4[2]; bf[nt2 * 2 + 1][1] = t4[3];
            }
            #pragma unroll
            for (int nt = 0; nt < 8; nt++)
                mma_f16(o[nt], af, bf[nt]);
        }
        __syncthreads();
    }

    float il_lo = 1.0f / l_lo, il_hi = 1.0f / l_hi;
    int row_lo = q0 + w * 16 + g;
    int row_hi = row_lo + 8;
    #pragma unroll
    for (int nt = 0; nt < 8; nt++) {
        int col = h * DHEAD + nt * 8 + tig * 2;
        *(__half2*)&O[((long)(b * NQ + row_lo) << 10) + col] =
            __floats2half2_rn(o[nt][0] * il_lo, o[nt][1] * il_lo);
        *(__half2*)&O[((long)(b * NQ + row_hi) << 10) + col] =
            __floats2half2_rn(o[nt][2] * il_hi, o[nt][3] * il_hi);
    }
}

// ---------------------------------------------------------------------------
// Launch
// ---------------------------------------------------------------------------
extern "C" void kernel_launch(void* const* d_in, const int* in_sizes, int n_in,
                              void* d_out, int out_size)
{
    const float* query     = (const float*)d_in[0];
    const float* key_value = (const float*)d_in[1];
    const float* Wq = (const float*)d_in[2];
    const float* bq = (const float*)d_in[3];
    const float* Wk = (const float*)d_in[4];
    const float* bk = (const float*)d_in[5];
    const float* Wv = (const float*)d_in[6];
    const float* bv = (const float*)d_in[7];
    const float* Wo = (const float*)d_in[8];
    const float* bo = (const float*)d_in[9];
    const float* g1 = (const float*)d_in[10];
    const float* b1 = (const float*)d_in[11];
    const float* g2 = (const float*)d_in[12];
    const float* b2 = (const float*)d_in[13];
    const float* gate_up = (const float*)d_in[14];
    const float* down    = (const float*)d_in[15];
    float* out = (float*)d_out;

    __half *xh, *qh, *kh, *vt, *kvh, *ctxh, *heh, *inth;
    __half *wqt, *wkt, *wvt, *wot, *gut, *dnt;
    float *res;
    cudaGetSymbolAddress((void**)&xh,   g_xh);
    cudaGetSymbolAddress((void**)&qh,   g_qh);
    cudaGetSymbolAddress((void**)&kh,   g_kh);
    cudaGetSymbolAddress((void**)&vt,   g_vt);
    cudaGetSymbolAddress((void**)&kvh,  g_kvh);
    cudaGetSymbolAddress((void**)&ctxh, g_ctxh);
    cudaGetSymbolAddress((void**)&res,  g_res);
    cudaGetSymbolAddress((void**)&heh,  g_heh);
    cudaGetSymbolAddress((void**)&inth, g_inth);
    cudaGetSymbolAddress((void**)&wqt,  g_wqt);
    cudaGetSymbolAddress((void**)&wkt,  g_wkt);
    cudaGetSymbolAddress((void**)&wvt,  g_wvt);
    cudaGetSymbolAddress((void**)&wot,  g_wot);
    cudaGetSymbolAddress((void**)&gut,  g_gut);
    cudaGetSymbolAddress((void**)&dnt,  g_dnt);

    cudaFuncSetAttribute(flash_h,
        cudaFuncAttributeMaxDynamicSharedMemorySize, FL_SMEM);
    cudaFuncSetAttribute(tc_gemm_h,
        cudaFuncAttributeMaxDynamicSharedMemorySize, GM_SMEM);

    // 0. weight transpose+cvt (4 H x H in one launch), MoE weights, kv cvt
    TP4 tp;
    tp.in[0] = Wq; tp.out[0] = wqt;
    tp.in[1] = Wk; tp.out[1] = wkt;
    tp.in[2] = Wv; tp.out[2] = wvt;
    tp.in[3] = Wo; tp.out[3] = wot;
    transpose4_kernel<<<dim3(32, 32, 4), 256>>>(tp, HDIM, HDIM);
    transpose_cvt_kernel<<<dim3(64, 32, NEXP), 256>>>(gate_up, gut, HDIM, 2 * IDIM, 1);
    transpose_cvt_kernel<<<dim3(32, 32, NEXP), 256>>>(down, dnt, IDIM, HDIM, 0);
    cvt_kernel<<<(BATCH * NKV * HDIM / 4) / 256, 256>>>(key_value, kvh);

    // 1. LN1 -> fp16
    ln_kernel<<<BATCH * NQ, 256>>>(query, g1, b1, xh, 0);

    // 2-4. Q/K/V projections (V writes transposed into vt directly)
    tc_gemm_h<<<dim3(8, 32), 256, GM_SMEM>>>(xh,  wqt, bq, nullptr, qh,
                                             BATCH * NQ, HDIM, 0, 0, 0, 0);
    tc_gemm_h<<<dim3(8, 64), 256, GM_SMEM>>>(kvh, wkt, bk, nullptr, kh,
                                             BATCH * NKV, HDIM, 0, 0, 0, 0);
    tc_gemm_h<<<dim3(8, 64), 256, GM_SMEM>>>(kvh, wvt, bv, nullptr, vt,
                                             BATCH * NKV, HDIM, 4, 0, 0, 0);

    // 5. attention
    flash_h<<<dim3(NQ / 128, NH, BATCH), 256, FL_SMEM>>>(qh, kh, vt, ctxh);

    // 6. O proj + residual -> res (fp32)
    tc_gemm_h<<<dim3(8, 32), 256, GM_SMEM>>>(ctxh, wot, bo, query, res,
                                             BATCH * NQ, HDIM, 1, 0, 0, 0);

    // 7. LN2 (expert-grouped scatter) -> fp16
    ln_kernel<<<BATCH * NQ, 256>>>(res, g2, b2, heh, 1);

    // 8. gate_up GEMM + fused SiLU (per expert) -> inth (half)
    tc_gemm_h<<<dim3(16, 8, NEXP), 256, GM_SMEM>>>(heh, gut, nullptr, nullptr, inth,
        BATCH * NQ / NEXP, 2 * IDIM, 3,
        (long)(BATCH * NQ / NEXP) * HDIM,
        (long)2 * IDIM * HDIM,
        (long)(BATCH * NQ / NEXP) * IDIM);

    // 9. down GEMM, scatter + residual -> out (fp32)
    tc_gemm_h<<<dim3(8, 8, NEXP), 256, GM_SMEM>>>(inth, dnt, nullptr, res, out,
        BATCH * NQ / NEXP, HDIM, 2,
        (long)(BATCH * NQ / NEXP) * IDIM,
        (long)HDIM * IDIM, 0);
}